// round 1
// baseline (speedup 1.0000x reference)
#include <cuda_runtime.h>
#include <math.h>

#define BATCH 2
#define NTOK  8000
#define NP1   8001
#define PADN  191
#define NPAD  8192
#define DM    512
#define DIN   1024
#define NH    8
#define DH    64
#define NLM   256
#define LPER  32
#define BHN   16
#define CONVK 33
#define TD    1536

// ---------------- scratch (device globals; no allocation allowed) ----------------
__device__ float g_h   [(long long)BATCH*NPAD*DM];
__device__ float g_xln [(long long)BATCH*NPAD*DM];
__device__ float g_qkv [(long long)BATCH*NPAD*TD];
__device__ float g_ql  [(long long)BHN*NLM*DH];
__device__ float g_kl  [(long long)BHN*NLM*DH];
__device__ float g_a1  [(long long)BHN*NPAD*NLM];
__device__ float g_a3  [(long long)BHN*NLM*NPAD];   // reused as a1z afterwards
__device__ float g_a2  [(long long)BHN*NLM*NLM];
__device__ float g_z   [(long long)BHN*NLM*NLM];
__device__ float g_z2  [(long long)BHN*NLM*NLM];
__device__ float g_xz  [(long long)BHN*NLM*NLM];
__device__ float g_t   [(long long)BHN*NLM*NLM];
__device__ float g_t2  [(long long)BHN*NLM*NLM];
__device__ float g_a3v [(long long)BHN*NLM*DH];
__device__ float g_a3vp[(long long)16*BHN*NLM*DH];
__device__ float g_outh[(long long)BHN*NPAD*DH];
__device__ float g_cat [(long long)BATCH*NPAD*DM];
__device__ int   g_maxrow;
__device__ int   g_maxcol;

// ---------------- reduction helpers (blockDim.x == 256) ----------------
__device__ __forceinline__ float blockReduceSum(float v, float* sh) {
    #pragma unroll
    for (int o = 16; o; o >>= 1) v += __shfl_xor_sync(0xffffffffu, v, o);
    int w = threadIdx.x >> 5;
    if ((threadIdx.x & 31) == 0) sh[w] = v;
    __syncthreads();
    if (threadIdx.x < 8) {
        v = sh[threadIdx.x];
        #pragma unroll
        for (int o = 4; o; o >>= 1) v += __shfl_xor_sync(0xffu, v, o);
        if (threadIdx.x == 0) sh[0] = v;
    }
    __syncthreads();
    float r = sh[0];
    __syncthreads();
    return r;
}
__device__ __forceinline__ float blockReduceMax(float v, float* sh) {
    #pragma unroll
    for (int o = 16; o; o >>= 1) v = fmaxf(v, __shfl_xor_sync(0xffffffffu, v, o));
    int w = threadIdx.x >> 5;
    if ((threadIdx.x & 31) == 0) sh[w] = v;
    __syncthreads();
    if (threadIdx.x < 8) {
        v = sh[threadIdx.x];
        #pragma unroll
        for (int o = 4; o; o >>= 1) v = fmaxf(v, __shfl_xor_sync(0xffu, v, o));
        if (threadIdx.x == 0) sh[0] = v;
    }
    __syncthreads();
    float r = sh[0];
    __syncthreads();
    return r;
}

// ---------------- generic batched SGEMM: C = alpha*A@B (+bias)(+relu)(+=C) ----------------
// Batch offset for A/B: off(batch) = (batch/cnt)*outer + (batch%cnt)*inner
// transB: B given as [N,K] row-major (we compute A @ B^T)
// splitK>1: write alpha*partial to C + split*partStride (no bias/relu/accum)
__global__ void __launch_bounds__(256) gemm_kernel(
    const float* __restrict__ A, const float* __restrict__ B, float* __restrict__ C,
    int Mn, int Nn, int Kn, int lda, int ldb, int ldc,
    long long aOuter, long long aInner, int aCnt,
    long long bOuter, long long bInner, int bCnt,
    long long cStride,
    float alpha, const float* __restrict__ bias,
    int relu, int accum, int transB, int splitK, long long partStride)
{
    int bz = blockIdx.z;
    int batch = bz / splitK;
    int split = bz - batch * splitK;
    const float* Ab = A + (long long)(batch / aCnt) * aOuter + (long long)(batch % aCnt) * aInner;
    const float* Bb = B + (long long)(batch / bCnt) * bOuter + (long long)(batch % bCnt) * bInner;
    float* Cb = C + (long long)batch * cStride + (long long)split * partStride;
    int kPer = Kn / splitK;
    int kStart = split * kPer;

    __shared__ float As[16][68];
    __shared__ float Bs[16][68];

    int tid = threadIdx.x;
    int tx = tid & 15, ty = tid >> 4;
    int rowBase = blockIdx.y << 6;
    int colBase = blockIdx.x << 6;

    float acc[4][4];
    #pragma unroll
    for (int i = 0; i < 4; i++)
        #pragma unroll
        for (int j = 0; j < 4; j++) acc[i][j] = 0.f;

    for (int k0 = 0; k0 < kPer; k0 += 16) {
        #pragma unroll
        for (int i = 0; i < 4; i++) {
            int idx = tid + (i << 8);
            int am = idx >> 4, ak = idx & 15;
            int gr = rowBase + am;
            float v = 0.f;
            if (gr < Mn) v = Ab[(long long)gr * lda + (kStart + k0 + ak)];
            As[ak][am] = v;
        }
        if (!transB) {
            #pragma unroll
            for (int i = 0; i < 4; i++) {
                int idx = tid + (i << 8);
                int bn = idx & 63, bk = idx >> 6;
                int gc = colBase + bn;
                float v = 0.f;
                if (gc < Nn) v = Bb[(long long)(kStart + k0 + bk) * ldb + gc];
                Bs[bk][bn] = v;
            }
        } else {
            #pragma unroll
            for (int i = 0; i < 4; i++) {
                int idx = tid + (i << 8);
                int bk = idx & 15, bn = idx >> 4;
                int gc = colBase + bn;
                float v = 0.f;
                if (gc < Nn) v = Bb[(long long)gc * ldb + (kStart + k0 + bk)];
                Bs[bk][bn] = v;
            }
        }
        __syncthreads();
        #pragma unroll
        for (int k = 0; k < 16; k++) {
            float4 ra4 = *reinterpret_cast<const float4*>(&As[k][ty << 2]);
            float4 rb4 = *reinterpret_cast<const float4*>(&Bs[k][tx << 2]);
            float ar[4] = {ra4.x, ra4.y, ra4.z, ra4.w};
            float br[4] = {rb4.x, rb4.y, rb4.z, rb4.w};
            #pragma unroll
            for (int i = 0; i < 4; i++)
                #pragma unroll
                for (int j = 0; j < 4; j++)
                    acc[i][j] = fmaf(ar[i], br[j], acc[i][j]);
        }
        __syncthreads();
    }
    #pragma unroll
    for (int i = 0; i < 4; i++) {
        int gr = rowBase + (ty << 2) + i;
        if (gr >= Mn) continue;
        #pragma unroll
        for (int j = 0; j < 4; j++) {
            int gc = colBase + (tx << 2) + j;
            if (gc >= Nn) continue;
            float v = alpha * acc[i][j];
            if (bias) v += bias[gc];
            if (relu) v = fmaxf(v, 0.f);
            long long off = (long long)gr * ldc + gc;
            if (accum) v += Cb[off];
            Cb[off] = v;
        }
    }
}

// ---------------- misc kernels ----------------
__global__ void init_h_kernel(const float* __restrict__ cls, float* __restrict__ h) {
    int r = blockIdx.x, b = blockIdx.y;
    float* o = h + ((long long)b * NPAD + r) * DM;
    for (int i = threadIdx.x; i < DM; i += 256) o[i] = (r == PADN) ? cls[i] : 0.f;
}

__global__ void layernorm_kernel(const float* __restrict__ in, float* __restrict__ out,
                                 const float* __restrict__ gam, const float* __restrict__ bet) {
    __shared__ float sh[8];
    long long row = blockIdx.x;
    int r = (int)(row % NPAD);
    float* o = out + row * DM;
    if (r < PADN) {
        for (int i = threadIdx.x; i < DM; i += 256) o[i] = 0.f;
        return;
    }
    const float* x = in + row * DM;
    float s = 0.f, s2 = 0.f;
    for (int i = threadIdx.x; i < DM; i += 256) { float v = x[i]; s += v; s2 += v * v; }
    s = blockReduceSum(s, sh);
    s2 = blockReduceSum(s2, sh);
    float mean = s / DM;
    float var = s2 / DM - mean * mean;
    float inv = rsqrtf(var + 1e-5f);
    for (int i = threadIdx.x; i < DM; i += 256) o[i] = (x[i] - mean) * inv * gam[i] + bet[i];
}

__global__ void landmark_kernel(const float* __restrict__ qkv,
                                float* __restrict__ ql, float* __restrict__ kl) {
    int m = blockIdx.x, bh = blockIdx.y;
    int b = bh >> 3, h = bh & 7;
    int d = threadIdx.x;  // 64 threads
    const float* base = qkv + (long long)b * NPAD * TD + (long long)m * LPER * TD + h * 64 + d;
    float sq = 0.f, sk = 0.f;
    #pragma unroll 4
    for (int r = 0; r < LPER; r++) {
        sq += base[(long long)r * TD];
        sk += base[(long long)r * TD + 512];
    }
    ql[((long long)bh * NLM + m) * DH + d] = sq * (1.f / LPER);
    kl[((long long)bh * NLM + m) * DH + d] = sk * (1.f / LPER);
}

__global__ void softmax_rows(float* __restrict__ data, int cols) {
    __shared__ float sh[8];
    long long row = blockIdx.x;
    float* x = data + row * (long long)cols;
    float m = -1e30f;
    for (int i = threadIdx.x; i < cols; i += 256) m = fmaxf(m, x[i]);
    m = blockReduceMax(m, sh);
    float s = 0.f;
    for (int i = threadIdx.x; i < cols; i += 256) { float e = expf(x[i] - m); x[i] = e; s += e; }
    s = blockReduceSum(s, sh);
    float inv = 1.f / s;
    for (int i = threadIdx.x; i < cols; i += 256) x[i] *= inv;
}

__global__ void reset_kernel() {
    if (threadIdx.x == 0) { g_maxrow = 0; g_maxcol = 0; }
}

__global__ void a2stats_kernel(const float* __restrict__ a2) {
    __shared__ float sh[8];
    int bh = blockIdx.x;
    const float* a = a2 + (long long)bh * NLM * NLM;
    int j = threadIdx.x;  // 256
    float cs = 0.f, rs = 0.f;
    for (int i = 0; i < NLM; i++) cs += a[(long long)i * NLM + j];
    const float* row = a + (long long)j * NLM;
    for (int i = 0; i < NLM; i++) rs += row[i];
    float cmax = blockReduceMax(cs, sh);
    float rmax = blockReduceMax(rs, sh);
    if (threadIdx.x == 0) {
        atomicMax(&g_maxcol, __float_as_int(cmax));
        atomicMax(&g_maxrow, __float_as_int(rmax));
    }
}

__global__ void z0_kernel(const float* __restrict__ a2, float* __restrict__ z) {
    __shared__ float tile[32][33];
    int bh = blockIdx.z;
    const float* a = a2 + (long long)bh * NLM * NLM;
    float* zz = z + (long long)bh * NLM * NLM;
    float inv = 1.f / (__int_as_float(g_maxrow) * __int_as_float(g_maxcol));
    int i0 = blockIdx.y * 32, j0 = blockIdx.x * 32;
    for (int r = threadIdx.y; r < 32; r += 8)
        tile[r][threadIdx.x] = a[(long long)(i0 + r) * NLM + j0 + threadIdx.x];
    __syncthreads();
    for (int r = threadIdx.y; r < 32; r += 8)
        zz[(long long)(j0 + r) * NLM + i0 + threadIdx.x] = tile[threadIdx.x][r] * inv;
}

// dst = c*I - src  (row-wise, 256 cols)
__global__ void diagsub_kernel(const float* __restrict__ src, float* __restrict__ dst, float c) {
    long long row = blockIdx.x;
    int i = (int)(row % NLM);
    int j = threadIdx.x;
    long long off = row * NLM + j;
    dst[off] = ((i == j) ? c : 0.f) - src[off];
}

__global__ void reduce16_kernel(const float* __restrict__ part, float* __restrict__ out) {
    long long i = (long long)blockIdx.x * 256 + threadIdx.x;
    const long long stride = (long long)BHN * NLM * DH;
    float s = 0.f;
    #pragma unroll
    for (int k = 0; k < 16; k++) s += part[k * stride + i];
    out[i] = s;
}

__global__ void conv_add_kernel(const float* __restrict__ qkv, const float* __restrict__ w,
                                float* __restrict__ outh) {
    int bh = blockIdx.y;
    int b = bh >> 3, h = bh & 7;
    int iBase = blockIdx.x * 64;
    __shared__ float sv[96][64];
    __shared__ float sw[CONVK];
    const float* vbase = qkv + (long long)b * NPAD * TD + 1024 + h * 64;
    int tid = threadIdx.x;
    for (int idx = tid; idx < 96 * 64; idx += 256) {
        int r = idx >> 6, d = idx & 63;
        int gi = iBase - 16 + r;
        sv[r][d] = (gi >= 0 && gi < NPAD) ? vbase[(long long)gi * TD + d] : 0.f;
    }
    if (tid < CONVK) sw[tid] = w[h * CONVK + tid];
    __syncthreads();
    float* out = outh + (long long)bh * NPAD * DH + (long long)iBase * DH;
    for (int idx = tid; idx < 64 * 64; idx += 256) {
        int r = idx >> 6, d = idx & 63;
        float s = 0.f;
        #pragma unroll
        for (int t = 0; t < CONVK; t++) s += sw[t] * sv[r + t][d];
        out[r * 64 + d] += s;
    }
}

__global__ void merge_kernel(const float* __restrict__ outh, float* __restrict__ cat) {
    long long idx = (long long)blockIdx.x * 256 + threadIdx.x;  // total BATCH*NPAD*DM
    int d = (int)(idx & 63);
    int hh = (int)((idx >> 6) & 7);
    long long rest = idx >> 9;           // b*NPAD + i
    int i = (int)(rest & (NPAD - 1));
    int b = (int)(rest >> 13);
    cat[idx] = outh[((long long)(b * NH + hh) * NPAD + i) * DH + d];
}

__global__ void final_kernel(const float* __restrict__ h, const float* __restrict__ gam,
                             const float* __restrict__ bet, const float* __restrict__ w2,
                             const float* __restrict__ b2, float* __restrict__ out) {
    __shared__ float sh[8];
    int b = blockIdx.x;
    const float* x = h + ((long long)b * NPAD + PADN) * DM;
    float s = 0.f, s2 = 0.f;
    for (int i = threadIdx.x; i < DM; i += 256) { float v = x[i]; s += v; s2 += v * v; }
    s = blockReduceSum(s, sh);
    s2 = blockReduceSum(s2, sh);
    float mean = s / DM;
    float var = s2 / DM - mean * mean;
    float inv = rsqrtf(var + 1e-5f);
    float p0 = 0.f, p1 = 0.f;
    for (int i = threadIdx.x; i < DM; i += 256) {
        float hn = (x[i] - mean) * inv * gam[i] + bet[i];
        p0 += hn * w2[2 * i];
        p1 += hn * w2[2 * i + 1];
    }
    p0 = blockReduceSum(p0, sh);
    p1 = blockReduceSum(p1, sh);
    if (threadIdx.x == 0) {
        float l0 = p0 + b2[0], l1 = p1 + b2[1];
        float mx = fmaxf(l0, l1);
        float e0 = expf(l0 - mx), e1 = expf(l1 - mx);
        float si = 1.f / (e0 + e1);
        out[b * 2 + 0] = l0;
        out[b * 2 + 1] = l1;
        out[4 + b * 2 + 0] = e0 * si;
        out[4 + b * 2 + 1] = e1 * si;
        out[8 + b] = (l1 > l0) ? 1.f : 0.f;
    }
}

// ---------------- host side ----------------
static void launch_gemm(const float* A, const float* B, float* C,
                        int M, int N, int K, int lda, int ldb, int ldc,
                        long long aO, long long aI, int aC,
                        long long bO, long long bI, int bC,
                        long long cS, int batches, float alpha,
                        const float* bias, int relu, int accum, int transB,
                        int splitK = 1, long long partStride = 0) {
    dim3 grid((N + 63) / 64, (M + 63) / 64, batches * splitK);
    gemm_kernel<<<grid, 256>>>(A, B, C, M, N, K, lda, ldb, ldc,
                               aO, aI, aC, bO, bI, bC, cS, alpha, bias,
                               relu, accum, transB, splitK, partStride);
}

#define SYM(p, s) do { void* _t; cudaGetSymbolAddress(&_t, s); p = (float*)_t; } while (0)

extern "C" void kernel_launch(void* const* d_in, const int* in_sizes, int n_in,
                              void* d_out, int out_size) {
    const float* feats = (const float*)d_in[0];
    const float* fc1_w = (const float*)d_in[1];
    const float* fc1_b = (const float*)d_in[2];
    const float* cls   = (const float*)d_in[3];
    const float* lng[2]   = {(const float*)d_in[4],  (const float*)d_in[10]};
    const float* lnb[2]   = {(const float*)d_in[5],  (const float*)d_in[11]};
    const float* qkvw[2]  = {(const float*)d_in[6],  (const float*)d_in[12]};
    const float* outw[2]  = {(const float*)d_in[7],  (const float*)d_in[13]};
    const float* outb[2]  = {(const float*)d_in[8],  (const float*)d_in[14]};
    const float* convw[2] = {(const float*)d_in[9],  (const float*)d_in[15]};
    const float* nfg  = (const float*)d_in[16];
    const float* nfb  = (const float*)d_in[17];
    const float* fc2w = (const float*)d_in[18];
    const float* fc2b = (const float*)d_in[19];

    float *h, *xln, *qkv, *ql, *kl, *a1, *a3, *a2, *z, *z2, *xz, *t, *t2, *a3v, *a3vp, *outh, *cat;
    SYM(h, g_h); SYM(xln, g_xln); SYM(qkv, g_qkv); SYM(ql, g_ql); SYM(kl, g_kl);
    SYM(a1, g_a1); SYM(a3, g_a3); SYM(a2, g_a2); SYM(z, g_z); SYM(z2, g_z2);
    SYM(xz, g_xz); SYM(t, g_t); SYM(t2, g_t2); SYM(a3v, g_a3v); SYM(a3vp, g_a3vp);
    SYM(outh, g_outh); SYM(cat, g_cat);

    // 1. init h: zero pad rows, cls at row PADN
    init_h_kernel<<<dim3(PADN + 1, BATCH), 256>>>(cls, h);

    // 2. fc1 + relu -> h rows PADN+1..
    launch_gemm(feats, fc1_w, h + (long long)(PADN + 1) * DM,
                NTOK, DM, DIN, DIN, DM, DM,
                (long long)NTOK * DIN, 0, 1, 0, 0, 1,
                (long long)NPAD * DM, BATCH, 1.f, fc1_b, 1, 0, 0);

    const long long MM = (long long)NLM * NLM;

    for (int l = 0; l < 2; l++) {
        // layernorm (+ zero pad rows of xln)
        layernorm_kernel<<<BATCH * NPAD, 256>>>(h, xln, lng[l], lnb[l]);

        // qkv
        launch_gemm(xln, qkvw[l], qkv, NPAD, TD, DM, DM, TD, TD,
                    (long long)NPAD * DM, 0, 1, 0, 0, 1,
                    (long long)NPAD * TD, BATCH, 1.f, nullptr, 0, 0, 0);

        // landmark means
        landmark_kernel<<<dim3(NLM, BHN), 64>>>(qkv, ql, kl);

        // a1 = softmax(0.125 * Q @ k_l^T)   [bh, NPAD, NLM]
        launch_gemm(qkv, kl, a1, NPAD, NLM, DH, TD, DH, NLM,
                    (long long)NPAD * TD, 64, NH,
                    (long long)NLM * DH, 0, 1,
                    (long long)NPAD * NLM, BHN, 0.125f, nullptr, 0, 0, 1);
        softmax_rows<<<BHN * NPAD, 256>>>(a1, NLM);

        // a2 = softmax(0.125 * q_l @ k_l^T)  [bh, NLM, NLM]
        launch_gemm(ql, kl, a2, NLM, NLM, DH, DH, DH, NLM,
                    (long long)NLM * DH, 0, 1,
                    (long long)NLM * DH, 0, 1,
                    MM, BHN, 0.125f, nullptr, 0, 0, 1);
        softmax_rows<<<BHN * NLM, 256>>>(a2, NLM);

        // a3 = softmax(0.125 * q_l @ K^T)    [bh, NLM, NPAD]
        launch_gemm(ql, qkv + DM, a3, NLM, NPAD, DH, DH, TD, NPAD,
                    (long long)NLM * DH, 0, 1,
                    (long long)NPAD * TD, 64, NH,
                    (long long)NLM * NPAD, BHN, 0.125f, nullptr, 0, 0, 1);
        softmax_rows<<<BHN * NLM, 256>>>(a3, NPAD);

        // pinv(a2): z0 = a2^T / (max rowsum * max colsum); 6 Newton iterations
        reset_kernel<<<1, 32>>>();
        a2stats_kernel<<<BHN, 256>>>(a2);
        z0_kernel<<<dim3(8, 8, BHN), dim3(32, 8)>>>(a2, z);
        float* zc = z;
        float* zn = z2;
        for (int it = 0; it < 6; it++) {
            launch_gemm(a2, zc, xz, NLM, NLM, NLM, NLM, NLM, NLM,
                        MM, 0, 1, MM, 0, 1, MM, BHN, 1.f, nullptr, 0, 0, 0);
            diagsub_kernel<<<BHN * NLM, 256>>>(xz, t, 7.f);
            launch_gemm(xz, t, t2, NLM, NLM, NLM, NLM, NLM, NLM,
                        MM, 0, 1, MM, 0, 1, MM, BHN, 1.f, nullptr, 0, 0, 0);
            diagsub_kernel<<<BHN * NLM, 256>>>(t2, t2, 15.f);
            launch_gemm(xz, t2, t, NLM, NLM, NLM, NLM, NLM, NLM,
                        MM, 0, 1, MM, 0, 1, MM, BHN, 1.f, nullptr, 0, 0, 0);
            diagsub_kernel<<<BHN * NLM, 256>>>(t, t, 13.f);
            launch_gemm(zc, t, zn, NLM, NLM, NLM, NLM, NLM, NLM,
                        MM, 0, 1, MM, 0, 1, MM, BHN, 0.25f, nullptr, 0, 0, 0);
            float* tmp = zc; zc = zn; zn = tmp;
        }

        // a3v = a3 @ V   (split-K 16 + deterministic reduce)
        launch_gemm(a3, qkv + 2 * DM, a3vp, NLM, DH, NPAD, NPAD, TD, DH,
                    (long long)NLM * NPAD, 0, 1,
                    (long long)NPAD * TD, 64, NH,
                    (long long)NLM * DH, BHN, 1.f, nullptr, 0, 0, 0,
                    16, (long long)BHN * NLM * DH);
        reduce16_kernel<<<(BHN * NLM * DH) / 256, 256>>>(a3vp, a3v);

        // a1z = a1 @ z   (reuse a3 buffer)
        launch_gemm(a1, zc, a3, NPAD, NLM, NLM, NLM, NLM, NLM,
                    (long long)NPAD * NLM, 0, 1, MM, 0, 1,
                    (long long)NPAD * NLM, BHN, 1.f, nullptr, 0, 0, 0);

        // outh = a1z @ a3v
        launch_gemm(a3, a3v, outh, NPAD, DH, NLM, NLM, DH, DH,
                    (long long)NPAD * NLM, 0, 1,
                    (long long)NLM * DH, 0, 1,
                    (long long)NPAD * DH, BHN, 1.f, nullptr, 0, 0, 0);

        // depthwise conv residual on V
        conv_add_kernel<<<dim3(NPAD / 64, BHN), 256>>>(qkv, convw[l], outh);

        // merge heads -> cat [B, NPAD, DM]
        merge_kernel<<<(int)(((long long)BATCH * NPAD * DM) / 256), 256>>>(outh, cat);

        // output projection, accumulate into residual stream (real rows only)
        launch_gemm(cat + (long long)PADN * DM, outw[l], h + (long long)PADN * DM,
                    NP1, DM, DM, DM, DM, DM,
                    (long long)NPAD * DM, 0, 1, 0, 0, 1,
                    (long long)NPAD * DM, BATCH, 1.f, outb[l], 0, 1, 0);
    }

    // final: LN(cls) -> fc2 -> logits/probs/argmax
    final_kernel<<<BATCH, 256>>>(h, nfg, nfb, fc2w, fc2b, (float*)d_out);
}

// round 2
// speedup vs baseline: 1.7186x; 1.7186x over previous
#include <cuda_runtime.h>
#include <cuda_bf16.h>
#include <math.h>

#define BATCH 2
#define NTOK  8000
#define NP1   8001
#define PADN  191
#define NPAD  8192
#define DM    512
#define DIN   1024
#define NH    8
#define DH    64
#define NLM   256
#define LPER  32
#define BHN   16
#define CONVK 33
#define TD    1536

// ---------------- scratch (device globals; no allocation allowed) ----------------
__device__ float g_h   [(long long)BATCH*NPAD*DM];
__device__ float g_xln [(long long)BATCH*NPAD*DM];
__device__ float g_qkv [(long long)BATCH*NPAD*TD];
__device__ float g_ql  [(long long)BHN*NLM*DH];
__device__ float g_kl  [(long long)BHN*NLM*DH];
__device__ float g_a1  [(long long)BHN*NPAD*NLM];
__device__ float g_a3  [(long long)BHN*NLM*NPAD];
__device__ float g_a2  [(long long)BHN*NLM*NLM];
__device__ float g_z   [(long long)BHN*NLM*NLM];
__device__ float g_z2  [(long long)BHN*NLM*NLM];
__device__ float g_xz  [(long long)BHN*NLM*NLM];
__device__ float g_t   [(long long)BHN*NLM*NLM];
__device__ float g_t2  [(long long)BHN*NLM*NLM];
__device__ float g_a3v [(long long)BHN*NLM*DH];
__device__ float g_w   [(long long)BHN*NLM*DH];
__device__ float g_a3vp[(long long)16*BHN*NLM*DH];
__device__ float g_outh[(long long)BHN*NPAD*DH];
__device__ float g_cat [(long long)BATCH*NPAD*DM];
__device__ int   g_maxrow;
__device__ int   g_maxcol;

// ---------------- reduction helpers (blockDim.x == 256) ----------------
__device__ __forceinline__ float blockReduceSum(float v, float* sh) {
    #pragma unroll
    for (int o = 16; o; o >>= 1) v += __shfl_xor_sync(0xffffffffu, v, o);
    int w = threadIdx.x >> 5;
    if ((threadIdx.x & 31) == 0) sh[w] = v;
    __syncthreads();
    if (threadIdx.x < 8) {
        v = sh[threadIdx.x];
        #pragma unroll
        for (int o = 4; o; o >>= 1) v += __shfl_xor_sync(0xffu, v, o);
        if (threadIdx.x == 0) sh[0] = v;
    }
    __syncthreads();
    float r = sh[0];
    __syncthreads();
    return r;
}
__device__ __forceinline__ float blockReduceMax(float v, float* sh) {
    #pragma unroll
    for (int o = 16; o; o >>= 1) v = fmaxf(v, __shfl_xor_sync(0xffffffffu, v, o));
    int w = threadIdx.x >> 5;
    if ((threadIdx.x & 31) == 0) sh[w] = v;
    __syncthreads();
    if (threadIdx.x < 8) {
        v = sh[threadIdx.x];
        #pragma unroll
        for (int o = 4; o; o >>= 1) v = fmaxf(v, __shfl_xor_sync(0xffu, v, o));
        if (threadIdx.x == 0) sh[0] = v;
    }
    __syncthreads();
    float r = sh[0];
    __syncthreads();
    return r;
}

// ---------------- bf16x3 tensor-core GEMM ----------------
// C = alpha * A @ B(^T) (+bias)(+relu)(+=C), fp32 in/out, bf16x3 internally.
// Requirements: N % 64 == 0, K % (32*splitK)... (kPer % 32 == 0). M arbitrary.
// Block tile 128x64, 8 warps of 32x32, BK=32.

__device__ __forceinline__ void mma16816(float* c, const unsigned* a, const unsigned* b) {
    asm volatile(
        "mma.sync.aligned.m16n8k16.row.col.f32.bf16.bf16.f32 "
        "{%0,%1,%2,%3},{%4,%5,%6,%7},{%8,%9},{%0,%1,%2,%3};\n"
        : "+f"(c[0]), "+f"(c[1]), "+f"(c[2]), "+f"(c[3])
        : "r"(a[0]), "r"(a[1]), "r"(a[2]), "r"(a[3]), "r"(b[0]), "r"(b[1]));
}

__device__ __forceinline__ void split4(float4 v, unsigned& h01, unsigned& h23,
                                       unsigned& l01, unsigned& l23) {
    __nv_bfloat16 hx = __float2bfloat16(v.x), hy = __float2bfloat16(v.y);
    __nv_bfloat16 hz = __float2bfloat16(v.z), hw = __float2bfloat16(v.w);
    __nv_bfloat162 a; a.x = hx; a.y = hy;
    __nv_bfloat162 b; b.x = hz; b.y = hw;
    h01 = *reinterpret_cast<unsigned*>(&a);
    h23 = *reinterpret_cast<unsigned*>(&b);
    __nv_bfloat162 c;
    c.x = __float2bfloat16(v.x - __bfloat162float(hx));
    c.y = __float2bfloat16(v.y - __bfloat162float(hy));
    __nv_bfloat162 d;
    d.x = __float2bfloat16(v.z - __bfloat162float(hz));
    d.y = __float2bfloat16(v.w - __bfloat162float(hw));
    l01 = *reinterpret_cast<unsigned*>(&c);
    l23 = *reinterpret_cast<unsigned*>(&d);
}

__global__ void __launch_bounds__(256) gemm_kernel(
    const float* __restrict__ A, const float* __restrict__ B, float* __restrict__ C,
    int Mn, int Nn, int Kn, int lda, int ldb, int ldc,
    long long aOuter, long long aInner, int aCnt,
    long long bOuter, long long bInner, int bCnt,
    long long cStride,
    float alpha, const float* __restrict__ bias,
    int relu, int accum, int transB, int splitK, long long partStride)
{
    int bz = blockIdx.z;
    int batch = bz / splitK;
    int split = bz - batch * splitK;
    const float* Ab = A + (long long)(batch / aCnt) * aOuter + (long long)(batch % aCnt) * aInner;
    const float* Bb = B + (long long)(batch / bCnt) * bOuter + (long long)(batch % bCnt) * bInner;
    float* Cb = C + (long long)batch * cStride + (long long)split * partStride;
    int kPer = Kn / splitK;
    int kStart = split * kPer;

    __shared__ unsigned sA[2][128][18];   // [hi/lo][m][k/2]
    __shared__ unsigned sB[2][64][18];    // [hi/lo][n][k/2]

    int tid = threadIdx.x;
    int lane = tid & 31;
    int wid = tid >> 5;
    int warpM = (wid & 3) * 32;
    int warpN = (wid >> 2) * 32;
    int rowBase = blockIdx.y << 7;
    int colBase = blockIdx.x << 6;

    float acc[2][4][4];
    #pragma unroll
    for (int i = 0; i < 2; i++)
        #pragma unroll
        for (int j = 0; j < 4; j++)
            #pragma unroll
            for (int k = 0; k < 4; k++) acc[i][j][k] = 0.f;

    int q = lane & 3;
    int g = lane >> 2;

    for (int k0 = 0; k0 < kPer; k0 += 32) {
        // ---- stage A: 128 x 32 fp32 -> bf16 hi/lo
        #pragma unroll
        for (int j = 0; j < 4; j++) {
            int f = tid + (j << 8);
            int row = f >> 3, seg = f & 7;
            int gr = rowBase + row;
            float4 v = make_float4(0.f, 0.f, 0.f, 0.f);
            if (gr < Mn)
                v = *reinterpret_cast<const float4*>(Ab + (long long)gr * lda + kStart + k0 + seg * 4);
            unsigned h01, h23, l01, l23;
            split4(v, h01, h23, l01, l23);
            sA[0][row][seg * 2]     = h01;
            sA[0][row][seg * 2 + 1] = h23;
            sA[1][row][seg * 2]     = l01;
            sA[1][row][seg * 2 + 1] = l23;
        }
        // ---- stage B -> sB[n][k]
        if (transB) {
            #pragma unroll
            for (int j = 0; j < 2; j++) {
                int f = tid + (j << 8);
                int row = f >> 3, seg = f & 7;   // row = n
                float4 v = *reinterpret_cast<const float4*>(
                    Bb + (long long)(colBase + row) * ldb + kStart + k0 + seg * 4);
                unsigned h01, h23, l01, l23;
                split4(v, h01, h23, l01, l23);
                sB[0][row][seg * 2]     = h01;
                sB[0][row][seg * 2 + 1] = h23;
                sB[1][row][seg * 2]     = l01;
                sB[1][row][seg * 2 + 1] = l23;
            }
        } else {
            __nv_bfloat16* ph = reinterpret_cast<__nv_bfloat16*>(&sB[0][0][0]);
            __nv_bfloat16* pl = reinterpret_cast<__nv_bfloat16*>(&sB[1][0][0]);
            #pragma unroll
            for (int j = 0; j < 2; j++) {
                int f = tid + (j << 8);
                int kr = f >> 4, seg = f & 15;   // kr = k row, n = seg*4..
                float4 v = *reinterpret_cast<const float4*>(
                    Bb + (long long)(kStart + k0 + kr) * ldb + colBase + seg * 4);
                int n0 = seg * 4;
                float vv[4] = {v.x, v.y, v.z, v.w};
                #pragma unroll
                for (int e = 0; e < 4; e++) {
                    __nv_bfloat16 hb = __float2bfloat16(vv[e]);
                    ph[(n0 + e) * 36 + kr] = hb;
                    pl[(n0 + e) * 36 + kr] = __float2bfloat16(vv[e] - __bfloat162float(hb));
                }
            }
        }
        __syncthreads();

        #pragma unroll
        for (int ks = 0; ks < 2; ks++) {
            int k8 = ks * 8;
            unsigned af[2][2][4];
            #pragma unroll
            for (int mt = 0; mt < 2; mt++) {
                int r = warpM + mt * 16 + g;
                #pragma unroll
                for (int s = 0; s < 2; s++) {
                    af[s][mt][0] = sA[s][r][k8 + q];
                    af[s][mt][1] = sA[s][r + 8][k8 + q];
                    af[s][mt][2] = sA[s][r][k8 + q + 4];
                    af[s][mt][3] = sA[s][r + 8][k8 + q + 4];
                }
            }
            unsigned bfr[2][4][2];
            #pragma unroll
            for (int nt = 0; nt < 4; nt++) {
                int n = warpN + nt * 8 + g;
                #pragma unroll
                for (int s = 0; s < 2; s++) {
                    bfr[s][nt][0] = sB[s][n][k8 + q];
                    bfr[s][nt][1] = sB[s][n][k8 + q + 4];
                }
            }
            #pragma unroll
            for (int mt = 0; mt < 2; mt++)
                #pragma unroll
                for (int nt = 0; nt < 4; nt++) {
                    mma16816(acc[mt][nt], af[0][mt], bfr[0][nt]);   // hi*hi
                    mma16816(acc[mt][nt], af[0][mt], bfr[1][nt]);   // hi*lo
                    mma16816(acc[mt][nt], af[1][mt], bfr[0][nt]);   // lo*hi
                }
        }
        __syncthreads();
    }

    // ---- epilogue
    #pragma unroll
    for (int mt = 0; mt < 2; mt++) {
        #pragma unroll
        for (int nt = 0; nt < 4; nt++) {
            int r0 = rowBase + warpM + mt * 16 + g;
            int c0 = colBase + warpN + nt * 8 + q * 2;
            #pragma unroll
            for (int e = 0; e < 4; e++) {
                int gr = r0 + ((e >> 1) << 3);
                int gc = c0 + (e & 1);
                if (gr >= Mn) continue;
                float v = alpha * acc[mt][nt][e];
                if (bias) v += bias[gc];
                if (relu) v = fmaxf(v, 0.f);
                long long off = (long long)gr * ldc + gc;
                if (accum) v += Cb[off];
                Cb[off] = v;
            }
        }
    }
}

// ---------------- misc kernels ----------------
__global__ void init_h_kernel(const float* __restrict__ cls, float* __restrict__ h) {
    int r = blockIdx.x, b = blockIdx.y;
    float* o = h + ((long long)b * NPAD + r) * DM;
    for (int i = threadIdx.x; i < DM; i += 256) o[i] = (r == PADN) ? cls[i] : 0.f;
}

__global__ void layernorm_kernel(const float* __restrict__ in, float* __restrict__ out,
                                 const float* __restrict__ gam, const float* __restrict__ bet) {
    __shared__ float sh[8];
    long long row = blockIdx.x;
    int r = (int)(row % NPAD);
    float* o = out + row * DM;
    if (r < PADN) {
        for (int i = threadIdx.x; i < DM; i += 256) o[i] = 0.f;
        return;
    }
    const float* x = in + row * DM;
    float s = 0.f, s2 = 0.f;
    for (int i = threadIdx.x; i < DM; i += 256) { float v = x[i]; s += v; s2 += v * v; }
    s = blockReduceSum(s, sh);
    s2 = blockReduceSum(s2, sh);
    float mean = s / DM;
    float var = s2 / DM - mean * mean;
    float inv = rsqrtf(var + 1e-5f);
    for (int i = threadIdx.x; i < DM; i += 256) o[i] = (x[i] - mean) * inv * gam[i] + bet[i];
}

__global__ void landmark_kernel(const float* __restrict__ qkv,
                                float* __restrict__ ql, float* __restrict__ kl) {
    int m = blockIdx.x, bh = blockIdx.y;
    int b = bh >> 3, h = bh & 7;
    int d = threadIdx.x;
    const float* base = qkv + (long long)b * NPAD * TD + (long long)m * LPER * TD + h * 64 + d;
    float sq = 0.f, sk = 0.f;
    #pragma unroll 4
    for (int r = 0; r < LPER; r++) {
        sq += base[(long long)r * TD];
        sk += base[(long long)r * TD + 512];
    }
    ql[((long long)bh * NLM + m) * DH + d] = sq * (1.f / LPER);
    kl[((long long)bh * NLM + m) * DH + d] = sk * (1.f / LPER);
}

__global__ void softmax_rows(float* __restrict__ data, int cols) {
    __shared__ float sh[8];
    long long row = blockIdx.x;
    float* x = data + row * (long long)cols;
    float m = -1e30f;
    for (int i = threadIdx.x; i < cols; i += 256) m = fmaxf(m, x[i]);
    m = blockReduceMax(m, sh);
    float s = 0.f;
    for (int i = threadIdx.x; i < cols; i += 256) { float e = expf(x[i] - m); x[i] = e; s += e; }
    s = blockReduceSum(s, sh);
    float inv = 1.f / s;
    for (int i = threadIdx.x; i < cols; i += 256) x[i] *= inv;
}

__global__ void reset_kernel() {
    if (threadIdx.x == 0) { g_maxrow = 0; g_maxcol = 0; }
}

__global__ void a2stats_kernel(const float* __restrict__ a2) {
    __shared__ float sh[8];
    int bh = blockIdx.x;
    const float* a = a2 + (long long)bh * NLM * NLM;
    int j = threadIdx.x;
    float cs = 0.f, rs = 0.f;
    for (int i = 0; i < NLM; i++) cs += a[(long long)i * NLM + j];
    const float* row = a + (long long)j * NLM;
    for (int i = 0; i < NLM; i++) rs += row[i];
    float cmax = blockReduceMax(cs, sh);
    float rmax = blockReduceMax(rs, sh);
    if (threadIdx.x == 0) {
        atomicMax(&g_maxcol, __float_as_int(cmax));
        atomicMax(&g_maxrow, __float_as_int(rmax));
    }
}

__global__ void z0_kernel(const float* __restrict__ a2, float* __restrict__ z) {
    __shared__ float tile[32][33];
    int bh = blockIdx.z;
    const float* a = a2 + (long long)bh * NLM * NLM;
    float* zz = z + (long long)bh * NLM * NLM;
    float inv = 1.f / (__int_as_float(g_maxrow) * __int_as_float(g_maxcol));
    int i0 = blockIdx.y * 32, j0 = blockIdx.x * 32;
    for (int r = threadIdx.y; r < 32; r += 8)
        tile[r][threadIdx.x] = a[(long long)(i0 + r) * NLM + j0 + threadIdx.x];
    __syncthreads();
    for (int r = threadIdx.y; r < 32; r += 8)
        zz[(long long)(j0 + r) * NLM + i0 + threadIdx.x] = tile[threadIdx.x][r] * inv;
}

__global__ void diagsub_kernel(const float* __restrict__ src, float* __restrict__ dst, float c) {
    long long row = blockIdx.x;
    int i = (int)(row % NLM);
    int j = threadIdx.x;
    long long off = row * NLM + j;
    dst[off] = ((i == j) ? c : 0.f) - src[off];
}

__global__ void reduce16_kernel(const float* __restrict__ part, float* __restrict__ out) {
    long long i = (long long)blockIdx.x * 256 + threadIdx.x;
    const long long stride = (long long)BHN * NLM * DH;
    float s = 0.f;
    #pragma unroll
    for (int k = 0; k < 16; k++) s += part[k * stride + i];
    out[i] = s;
}

__global__ void conv_add_kernel(const float* __restrict__ qkv, const float* __restrict__ w,
                                float* __restrict__ outh) {
    int bh = blockIdx.y;
    int b = bh >> 3, h = bh & 7;
    int iBase = blockIdx.x * 64;
    __shared__ float sv[96][64];
    __shared__ float sw[CONVK];
    const float* vbase = qkv + (long long)b * NPAD * TD + 1024 + h * 64;
    int tid = threadIdx.x;
    for (int idx = tid; idx < 96 * 64; idx += 256) {
        int r = idx >> 6, d = idx & 63;
        int gi = iBase - 16 + r;
        sv[r][d] = (gi >= 0 && gi < NPAD) ? vbase[(long long)gi * TD + d] : 0.f;
    }
    if (tid < CONVK) sw[tid] = w[h * CONVK + tid];
    __syncthreads();
    float* out = outh + (long long)bh * NPAD * DH + (long long)iBase * DH;
    for (int idx = tid; idx < 64 * 64; idx += 256) {
        int r = idx >> 6, d = idx & 63;
        float s = 0.f;
        #pragma unroll
        for (int t = 0; t < CONVK; t++) s += sw[t] * sv[r + t][d];
        out[r * 64 + d] += s;
    }
}

__global__ void merge_kernel(const float* __restrict__ outh, float* __restrict__ cat) {
    long long idx = (long long)blockIdx.x * 256 + threadIdx.x;
    int d = (int)(idx & 63);
    int hh = (int)((idx >> 6) & 7);
    long long rest = idx >> 9;
    int i = (int)(rest & (NPAD - 1));
    int b = (int)(rest >> 13);
    cat[idx] = outh[((long long)(b * NH + hh) * NPAD + i) * DH + d];
}

__global__ void final_kernel(const float* __restrict__ h, const float* __restrict__ gam,
                             const float* __restrict__ bet, const float* __restrict__ w2,
                             const float* __restrict__ b2, float* __restrict__ out) {
    __shared__ float sh[8];
    int b = blockIdx.x;
    const float* x = h + ((long long)b * NPAD + PADN) * DM;
    float s = 0.f, s2 = 0.f;
    for (int i = threadIdx.x; i < DM; i += 256) { float v = x[i]; s += v; s2 += v * v; }
    s = blockReduceSum(s, sh);
    s2 = blockReduceSum(s2, sh);
    float mean = s / DM;
    float var = s2 / DM - mean * mean;
    float inv = rsqrtf(var + 1e-5f);
    float p0 = 0.f, p1 = 0.f;
    for (int i = threadIdx.x; i < DM; i += 256) {
        float hn = (x[i] - mean) * inv * gam[i] + bet[i];
        p0 += hn * w2[2 * i];
        p1 += hn * w2[2 * i + 1];
    }
    p0 = blockReduceSum(p0, sh);
    p1 = blockReduceSum(p1, sh);
    if (threadIdx.x == 0) {
        float l0 = p0 + b2[0], l1 = p1 + b2[1];
        float mx = fmaxf(l0, l1);
        float e0 = expf(l0 - mx), e1 = expf(l1 - mx);
        float si = 1.f / (e0 + e1);
        out[b * 2 + 0] = l0;
        out[b * 2 + 1] = l1;
        out[4 + b * 2 + 0] = e0 * si;
        out[4 + b * 2 + 1] = e1 * si;
        out[8 + b] = (l1 > l0) ? 1.f : 0.f;
    }
}

// ---------------- host side ----------------
static void launch_gemm(const float* A, const float* B, float* C,
                        int M, int N, int K, int lda, int ldb, int ldc,
                        long long aO, long long aI, int aC,
                        long long bO, long long bI, int bC,
                        long long cS, int batches, float alpha,
                        const float* bias, int relu, int accum, int transB,
                        int splitK = 1, long long partStride = 0) {
    dim3 grid((N + 63) / 64, (M + 127) / 128, batches * splitK);
    gemm_kernel<<<grid, 256>>>(A, B, C, M, N, K, lda, ldb, ldc,
                               aO, aI, aC, bO, bI, bC, cS, alpha, bias,
                               relu, accum, transB, splitK, partStride);
}

#define SYM(p, s) do { void* _t; cudaGetSymbolAddress(&_t, s); p = (float*)_t; } while (0)

extern "C" void kernel_launch(void* const* d_in, const int* in_sizes, int n_in,
                              void* d_out, int out_size) {
    const float* feats = (const float*)d_in[0];
    const float* fc1_w = (const float*)d_in[1];
    const float* fc1_b = (const float*)d_in[2];
    const float* cls   = (const float*)d_in[3];
    const float* lng[2]   = {(const float*)d_in[4],  (const float*)d_in[10]};
    const float* lnb[2]   = {(const float*)d_in[5],  (const float*)d_in[11]};
    const float* qkvw[2]  = {(const float*)d_in[6],  (const float*)d_in[12]};
    const float* outw[2]  = {(const float*)d_in[7],  (const float*)d_in[13]};
    const float* outb[2]  = {(const float*)d_in[8],  (const float*)d_in[14]};
    const float* convw[2] = {(const float*)d_in[9],  (const float*)d_in[15]};
    const float* nfg  = (const float*)d_in[16];
    const float* nfb  = (const float*)d_in[17];
    const float* fc2w = (const float*)d_in[18];
    const float* fc2b = (const float*)d_in[19];

    float *h, *xln, *qkv, *ql, *kl, *a1, *a3, *a2, *z, *z2, *xz, *t, *t2, *a3v, *w, *a3vp, *outh, *cat;
    SYM(h, g_h); SYM(xln, g_xln); SYM(qkv, g_qkv); SYM(ql, g_ql); SYM(kl, g_kl);
    SYM(a1, g_a1); SYM(a3, g_a3); SYM(a2, g_a2); SYM(z, g_z); SYM(z2, g_z2);
    SYM(xz, g_xz); SYM(t, g_t); SYM(t2, g_t2); SYM(a3v, g_a3v); SYM(w, g_w);
    SYM(a3vp, g_a3vp); SYM(outh, g_outh); SYM(cat, g_cat);

    init_h_kernel<<<dim3(PADN + 1, BATCH), 256>>>(cls, h);

    // fc1 + relu
    launch_gemm(feats, fc1_w, h + (long long)(PADN + 1) * DM,
                NTOK, DM, DIN, DIN, DM, DM,
                (long long)NTOK * DIN, 0, 1, 0, 0, 1,
                (long long)NPAD * DM, BATCH, 1.f, fc1_b, 1, 0, 0);

    const long long MM = (long long)NLM * NLM;

    for (int l = 0; l < 2; l++) {
        layernorm_kernel<<<BATCH * NPAD, 256>>>(h, xln, lng[l], lnb[l]);

        // qkv
        launch_gemm(xln, qkvw[l], qkv, NPAD, TD, DM, DM, TD, TD,
                    (long long)NPAD * DM, 0, 1, 0, 0, 1,
                    (long long)NPAD * TD, BATCH, 1.f, nullptr, 0, 0, 0);

        landmark_kernel<<<dim3(NLM, BHN), 64>>>(qkv, ql, kl);

        // a1 = softmax(0.125 * Q @ k_l^T)
        launch_gemm(qkv, kl, a1, NPAD, NLM, DH, TD, DH, NLM,
                    (long long)NPAD * TD, 64, NH,
                    (long long)NLM * DH, 0, 1,
                    (long long)NPAD * NLM, BHN, 0.125f, nullptr, 0, 0, 1);
        softmax_rows<<<BHN * NPAD, 256>>>(a1, NLM);

        // a2 = softmax(0.125 * q_l @ k_l^T)
        launch_gemm(ql, kl, a2, NLM, NLM, DH, DH, DH, NLM,
                    (long long)NLM * DH, 0, 1,
                    (long long)NLM * DH, 0, 1,
                    MM, BHN, 0.125f, nullptr, 0, 0, 1);
        softmax_rows<<<BHN * NLM, 256>>>(a2, NLM);

        // a3 = softmax(0.125 * q_l @ K^T)
        launch_gemm(ql, qkv + DM, a3, NLM, NPAD, DH, DH, TD, NPAD,
                    (long long)NLM * DH, 0, 1,
                    (long long)NPAD * TD, 64, NH,
                    (long long)NLM * NPAD, BHN, 0.125f, nullptr, 0, 0, 1);
        softmax_rows<<<BHN * NLM, 256>>>(a3, NPAD);

        // pinv(a2)
        reset_kernel<<<1, 32>>>();
        a2stats_kernel<<<BHN, 256>>>(a2);
        z0_kernel<<<dim3(8, 8, BHN), dim3(32, 8)>>>(a2, z);
        float* zc = z;
        float* zn = z2;
        for (int it = 0; it < 6; it++) {
            launch_gemm(a2, zc, xz, NLM, NLM, NLM, NLM, NLM, NLM,
                        MM, 0, 1, MM, 0, 1, MM, BHN, 1.f, nullptr, 0, 0, 0);
            diagsub_kernel<<<BHN * NLM, 256>>>(xz, t, 7.f);
            launch_gemm(xz, t, t2, NLM, NLM, NLM, NLM, NLM, NLM,
                        MM, 0, 1, MM, 0, 1, MM, BHN, 1.f, nullptr, 0, 0, 0);
            diagsub_kernel<<<BHN * NLM, 256>>>(t2, t2, 15.f);
            launch_gemm(xz, t2, t, NLM, NLM, NLM, NLM, NLM, NLM,
                        MM, 0, 1, MM, 0, 1, MM, BHN, 1.f, nullptr, 0, 0, 0);
            diagsub_kernel<<<BHN * NLM, 256>>>(t, t, 13.f);
            launch_gemm(zc, t, zn, NLM, NLM, NLM, NLM, NLM, NLM,
                        MM, 0, 1, MM, 0, 1, MM, BHN, 0.25f, nullptr, 0, 0, 0);
            float* tmp = zc; zc = zn; zn = tmp;
        }

        // a3v = a3 @ V   (split-K 16 + deterministic reduce)
        launch_gemm(a3, qkv + 2 * DM, a3vp, NLM, DH, NPAD, NPAD, TD, DH,
                    (long long)NLM * NPAD, 0, 1,
                    (long long)NPAD * TD, 64, NH,
                    (long long)NLM * DH, BHN, 1.f, nullptr, 0, 0, 0,
                    16, (long long)BHN * NLM * DH);
        reduce16_kernel<<<(BHN * NLM * DH) / 256, 256>>>(a3vp, a3v);

        // w = pinv(a2) @ a3v   [256 x 64]  (associativity: a1@(z@a3v))
        launch_gemm(zc, a3v, w, NLM, DH, NLM, NLM, DH, DH,
                    MM, 0, 1,
                    (long long)NLM * DH, 0, 1,
                    (long long)NLM * DH, BHN, 1.f, nullptr, 0, 0, 0);

        // outh = a1 @ w
        launch_gemm(a1, w, outh, NPAD, DH, NLM, NLM, DH, DH,
                    (long long)NPAD * NLM, 0, 1,
                    (long long)NLM * DH, 0, 1,
                    (long long)NPAD * DH, BHN, 1.f, nullptr, 0, 0, 0);

        // depthwise conv residual on V
        conv_add_kernel<<<dim3(NPAD / 64, BHN), 256>>>(qkv, convw[l], outh);

        merge_kernel<<<(int)(((long long)BATCH * NPAD * DM) / 256), 256>>>(outh, cat);

        // output projection, accumulate into residual stream
        launch_gemm(cat + (long long)PADN * DM, outw[l], h + (long long)PADN * DM,
                    NP1, DM, DM, DM, DM, DM,
                    (long long)NPAD * DM, 0, 1, 0, 0, 1,
                    (long long)NPAD * DM, BATCH, 1.f, outb[l], 0, 1, 0);
    }

    final_kernel<<<BATCH, 256>>>(h, nfg, nfb, fc2w, fc2b, (float*)d_out);
}

// round 4
// speedup vs baseline: 2.3362x; 1.3594x over previous
#include <cuda_runtime.h>
#include <cuda_bf16.h>
#include <cstdint>
#include <math.h>

#define BATCH 2
#define NTOK  8000
#define NP1   8001
#define PADN  191
#define NPAD  8192
#define DM    512
#define DIN   1024
#define NH    8
#define DH    64
#define NLM   256
#define LPER  32
#define BHN   16
#define CONVK 33
#define TD    1536
#define BM    128
#define BK    32

// ---------------- scratch ----------------
__device__ float g_h   [(long long)BATCH*NPAD*DM];
__device__ float g_xln [(long long)BATCH*NPAD*DM];
__device__ float g_qkv [(long long)BATCH*NPAD*TD];
__device__ float g_ql  [(long long)BHN*NLM*DH];
__device__ float g_kl  [(long long)BHN*NLM*DH];
__device__ float g_a1  [(long long)BHN*NPAD*NLM];
__device__ float g_a3  [(long long)BHN*NLM*NPAD];
__device__ float g_a2  [(long long)BHN*NLM*NLM];
__device__ float g_z   [(long long)BHN*NLM*NLM];
__device__ float g_z2  [(long long)BHN*NLM*NLM];
__device__ float g_xz  [(long long)BHN*NLM*NLM];
__device__ float g_t   [(long long)BHN*NLM*NLM];
__device__ float g_t2  [(long long)BHN*NLM*NLM];
__device__ float g_a3v [(long long)BHN*NLM*DH];
__device__ float g_w   [(long long)BHN*NLM*DH];
__device__ float g_a3vp[(long long)16*BHN*NLM*DH];
__device__ float g_outh[(long long)BHN*NPAD*DH];
__device__ float g_cat [(long long)BATCH*NPAD*DM];
__device__ int   g_maxrow;
__device__ int   g_maxcol;

// ---------------- reductions ----------------
__device__ __forceinline__ float blockReduceSum(float v, float* sh) {
    #pragma unroll
    for (int o = 16; o; o >>= 1) v += __shfl_xor_sync(0xffffffffu, v, o);
    int w = threadIdx.x >> 5;
    if ((threadIdx.x & 31) == 0) sh[w] = v;
    __syncthreads();
    if (threadIdx.x < 8) {
        v = sh[threadIdx.x];
        #pragma unroll
        for (int o = 4; o; o >>= 1) v += __shfl_xor_sync(0xffu, v, o);
        if (threadIdx.x == 0) sh[0] = v;
    }
    __syncthreads();
    float r = sh[0];
    __syncthreads();
    return r;
}
__device__ __forceinline__ float blockReduceMax(float v, float* sh) {
    #pragma unroll
    for (int o = 16; o; o >>= 1) v = fmaxf(v, __shfl_xor_sync(0xffffffffu, v, o));
    int w = threadIdx.x >> 5;
    if ((threadIdx.x & 31) == 0) sh[w] = v;
    __syncthreads();
    if (threadIdx.x < 8) {
        v = sh[threadIdx.x];
        #pragma unroll
        for (int o = 4; o; o >>= 1) v = fmaxf(v, __shfl_xor_sync(0xffu, v, o));
        if (threadIdx.x == 0) sh[0] = v;
    }
    __syncthreads();
    float r = sh[0];
    __syncthreads();
    return r;
}

// ---------------- tensor-core helpers ----------------
__device__ __forceinline__ void mma16816(float* c, const unsigned* a, const unsigned* b) {
    asm volatile(
        "mma.sync.aligned.m16n8k16.row.col.f32.bf16.bf16.f32 "
        "{%0,%1,%2,%3},{%4,%5,%6,%7},{%8,%9},{%0,%1,%2,%3};\n"
        : "+f"(c[0]), "+f"(c[1]), "+f"(c[2]), "+f"(c[3])
        : "r"(a[0]), "r"(a[1]), "r"(a[2]), "r"(a[3]), "r"(b[0]), "r"(b[1]));
}
__device__ __forceinline__ void ldsm4(unsigned& r0, unsigned& r1, unsigned& r2, unsigned& r3,
                                      uint32_t addr) {
    asm volatile("ldmatrix.sync.aligned.m8n8.x4.shared.b16 {%0,%1,%2,%3}, [%4];\n"
                 : "=r"(r0), "=r"(r1), "=r"(r2), "=r"(r3) : "r"(addr));
}
__device__ __forceinline__ void ldsm4t(unsigned& r0, unsigned& r1, unsigned& r2, unsigned& r3,
                                       uint32_t addr) {
    asm volatile("ldmatrix.sync.aligned.m8n8.x4.trans.shared.b16 {%0,%1,%2,%3}, [%4];\n"
                 : "=r"(r0), "=r"(r1), "=r"(r2), "=r"(r3) : "r"(addr));
}
__device__ __forceinline__ void split2(float x, float y, unsigned& hi, unsigned& lo) {
    __nv_bfloat162 h = __floats2bfloat162_rn(x, y);
    __nv_bfloat162 l = __floats2bfloat162_rn(x - __bfloat162float(h.x),
                                             y - __bfloat162float(h.y));
    hi = *reinterpret_cast<unsigned*>(&h);
    lo = *reinterpret_cast<unsigned*>(&l);
}

// ---------------- tensor-core GEMM (bf16x3, fp32 io) ----------------
// C = alpha*A@B(^T) + diag*I (+bias)(+relu)(+=C); optional C2 = diag2*I - C.
// Constraints: N % BN == 0, (K/splitK) % 32 == 0. M arbitrary.
template<int BN, int WROWS, int WCOLS>
__global__ void __launch_bounds__(256) gemm_tc(
    const float* __restrict__ A, const float* __restrict__ B, float* __restrict__ C,
    int Mn, int Nn, int Kn, int lda, int ldb, int ldc,
    long long aOuter, long long aInner, int aCnt,
    long long bOuter, long long bInner, int bCnt,
    long long cStride, float alpha, const float* __restrict__ bias,
    int relu, int accum, int transB, int splitK, long long partStride,
    float diagVal, float* __restrict__ C2, float diag2)
{
    constexpr int WM = BM / WROWS;
    constexpr int WN = BN / WCOLS;
    constexpr int MT = WM / 16;
    constexpr int NT = WN / 8;
    constexpr int NTP = WN / 16;
    constexpr int NBJ = BN / 32;
    constexpr int KST = BN + 8;   // k-major B row stride (elements)

    int bz = blockIdx.z;
    int batch = bz / splitK;
    int split = bz - batch * splitK;
    const float* Ab = A + (long long)(batch / aCnt) * aOuter + (long long)(batch % aCnt) * aInner;
    const float* Bb = B + (long long)(batch / bCnt) * bOuter + (long long)(batch % bCnt) * bInner;
    float* Cb = C + (long long)batch * cStride + (long long)split * partStride;
    float* C2b = C2 ? C2 + (long long)batch * cStride : nullptr;
    int kPer = Kn / splitK;
    int kStart = split * kPer;

    __shared__ __align__(16) __nv_bfloat16 sA[2][BM][40];
    __shared__ __align__(16) __nv_bfloat16 sB[2 * BN * 40];

    uint32_t saBase = (uint32_t)__cvta_generic_to_shared(&sA[0][0][0]);
    uint32_t sbBase = (uint32_t)__cvta_generic_to_shared(&sB[0]);

    int tid = threadIdx.x;
    int lane = tid & 31;
    int wid = tid >> 5;
    int lt = lane & 7;
    int lg = lane >> 3;
    int warpM = (wid / WCOLS) * WM;
    int warpN = (wid % WCOLS) * WN;
    int rowBase = blockIdx.y * BM;
    int colBase = blockIdx.x * BN;

    float acc[MT][NT][4];
    #pragma unroll
    for (int i = 0; i < MT; i++)
        #pragma unroll
        for (int j = 0; j < NT; j++)
            #pragma unroll
            for (int e = 0; e < 4; e++) acc[i][j][e] = 0.f;

    int aRow = tid >> 3, aSeg = tid & 7;
    float4 va[4], vb[NBJ];

    auto ldgA = [&](int k0) {
        #pragma unroll
        for (int j = 0; j < 4; j++) {
            int gr = rowBase + aRow + j * 32;
            va[j] = make_float4(0.f, 0.f, 0.f, 0.f);
            if (gr < Mn)
                va[j] = *(const float4*)(Ab + (long long)gr * lda + kStart + k0 + aSeg * 4);
        }
    };
    auto ldgB = [&](int k0) {
        if (transB) {
            #pragma unroll
            for (int j = 0; j < NBJ; j++)
                vb[j] = *(const float4*)(Bb + (long long)(colBase + aRow + j * 32) * ldb +
                                         kStart + k0 + aSeg * 4);
        } else {
            #pragma unroll
            for (int j = 0; j < NBJ; j++) {
                int k, n0;
                if (BN == 128) { k = (tid >> 5) + j * 8;  n0 = (tid & 31) * 4; }
                else           { k = (tid >> 4) + j * 16; n0 = (tid & 15) * 4; }
                vb[j] = *(const float4*)(Bb + (long long)(kStart + k0 + k) * ldb + colBase + n0);
            }
        }
    };
    auto stsA = [&]() {
        #pragma unroll
        for (int j = 0; j < 4; j++) {
            int row = aRow + j * 32;
            unsigned h0, h1, l0, l1;
            split2(va[j].x, va[j].y, h0, l0);
            split2(va[j].z, va[j].w, h1, l1);
            *(uint2*)&sA[0][row][aSeg * 4] = make_uint2(h0, h1);
            *(uint2*)&sA[1][row][aSeg * 4] = make_uint2(l0, l1);
        }
    };
    auto stsB = [&]() {
        if (transB) {
            #pragma unroll
            for (int j = 0; j < NBJ; j++) {
                int row = aRow + j * 32;
                unsigned h0, h1, l0, l1;
                split2(vb[j].x, vb[j].y, h0, l0);
                split2(vb[j].z, vb[j].w, h1, l1);
                *(uint2*)&sB[(0 * BN + row) * 40 + aSeg * 4] = make_uint2(h0, h1);
                *(uint2*)&sB[(1 * BN + row) * 40 + aSeg * 4] = make_uint2(l0, l1);
            }
        } else {
            #pragma unroll
            for (int j = 0; j < NBJ; j++) {
                int k, n0;
                if (BN == 128) { k = (tid >> 5) + j * 8;  n0 = (tid & 31) * 4; }
                else           { k = (tid >> 4) + j * 16; n0 = (tid & 15) * 4; }
                unsigned h0, h1, l0, l1;
                split2(vb[j].x, vb[j].y, h0, l0);
                split2(vb[j].z, vb[j].w, h1, l1);
                *(uint2*)&sB[(0 * 32 + k) * KST + n0] = make_uint2(h0, h1);
                *(uint2*)&sB[(1 * 32 + k) * KST + n0] = make_uint2(l0, l1);
            }
        }
    };

    ldgA(0);
    ldgB(0);
    for (int k0 = 0; k0 < kPer; k0 += BK) {
        stsA();
        stsB();
        __syncthreads();
        if (k0 + BK < kPer) { ldgA(k0 + BK); ldgB(k0 + BK); }

        #pragma unroll
        for (int ks = 0; ks < 2; ks++) {
            int k8 = ks * 16;
            unsigned bh[NTP][4], bl[NTP][4];
            #pragma unroll
            for (int ntp = 0; ntp < NTP; ntp++) {
                if (transB) {
                    int n = warpN + ntp * 16 + lt + ((lg >> 1) << 3);
                    int kk = k8 + ((lg & 1) << 3);
                    ldsm4(bh[ntp][0], bh[ntp][1], bh[ntp][2], bh[ntp][3],
                          sbBase + (((0 * BN + n) * 40 + kk) << 1));
                    ldsm4(bl[ntp][0], bl[ntp][1], bl[ntp][2], bl[ntp][3],
                          sbBase + (((1 * BN + n) * 40 + kk) << 1));
                } else {
                    int k = k8 + lt + ((lg & 1) << 3);
                    int n = warpN + ntp * 16 + ((lg >> 1) << 3);
                    ldsm4t(bh[ntp][0], bh[ntp][1], bh[ntp][2], bh[ntp][3],
                           sbBase + (((0 * 32 + k) * KST + n) << 1));
                    ldsm4t(bl[ntp][0], bl[ntp][1], bl[ntp][2], bl[ntp][3],
                           sbBase + (((1 * 32 + k) * KST + n) << 1));
                }
            }
            #pragma unroll
            for (int mt = 0; mt < MT; mt++) {
                unsigned ah[4], al[4];
                int m = warpM + mt * 16 + lt + ((lg & 1) << 3);
                int kk = k8 + ((lg >> 1) << 3);
                ldsm4(ah[0], ah[1], ah[2], ah[3],
                      saBase + (((0 * BM + m) * 40 + kk) << 1));
                ldsm4(al[0], al[1], al[2], al[3],
                      saBase + (((1 * BM + m) * 40 + kk) << 1));
                #pragma unroll
                for (int nt = 0; nt < NT; nt++) {
                    const unsigned* ph = &bh[nt >> 1][(nt & 1) * 2];
                    const unsigned* pl = &bl[nt >> 1][(nt & 1) * 2];
                    mma16816(acc[mt][nt], ah, ph);
                    mma16816(acc[mt][nt], ah, pl);
                    mma16816(acc[mt][nt], al, ph);
                }
            }
        }
        __syncthreads();
    }

    int q = lane & 3, g = lane >> 2;
    #pragma unroll
    for (int mt = 0; mt < MT; mt++) {
        #pragma unroll
        for (int nt = 0; nt < NT; nt++) {
            int r0 = rowBase + warpM + mt * 16 + g;
            int c0 = colBase + warpN + nt * 8 + q * 2;
            #pragma unroll
            for (int e = 0; e < 4; e++) {
                int gr = r0 + ((e >> 1) << 3);
                int gc = c0 + (e & 1);
                if (gr >= Mn) continue;
                float v = alpha * acc[mt][nt][e];
                if (gr == gc) v += diagVal;
                if (bias) v += bias[gc];
                if (relu) v = fmaxf(v, 0.f);
                long long off = (long long)gr * ldc + gc;
                if (accum) v += Cb[off];
                Cb[off] = v;
                if (C2b) C2b[off] = ((gr == gc) ? diag2 : 0.f) - v;
            }
        }
    }
}

// ---------------- misc kernels ----------------
__global__ void init_h_kernel(const float* __restrict__ cls, float* __restrict__ h) {
    int r = blockIdx.x, b = blockIdx.y;
    float* o = h + ((long long)b * NPAD + r) * DM;
    for (int i = threadIdx.x; i < DM; i += 256) o[i] = (r == PADN) ? cls[i] : 0.f;
}

__global__ void layernorm_kernel(const float* __restrict__ in, float* __restrict__ out,
                                 const float* __restrict__ gam, const float* __restrict__ bet) {
    __shared__ float sh[8];
    long long row = blockIdx.x;
    int r = (int)(row % NPAD);
    float* o = out + row * DM;
    if (r < PADN) {
        for (int i = threadIdx.x; i < DM; i += 256) o[i] = 0.f;
        return;
    }
    const float* x = in + row * DM;
    float s = 0.f, s2 = 0.f;
    for (int i = threadIdx.x; i < DM; i += 256) { float v = x[i]; s += v; s2 += v * v; }
    s = blockReduceSum(s, sh);
    s2 = blockReduceSum(s2, sh);
    float mean = s / DM;
    float var = s2 / DM - mean * mean;
    float inv = rsqrtf(var + 1e-5f);
    for (int i = threadIdx.x; i < DM; i += 256) o[i] = (x[i] - mean) * inv * gam[i] + bet[i];
}

__global__ void landmark_kernel(const float* __restrict__ qkv,
                                float* __restrict__ ql, float* __restrict__ kl) {
    int m = blockIdx.x, bh = blockIdx.y;
    int b = bh >> 3, h = bh & 7;
    int d = threadIdx.x;
    const float* base = qkv + (long long)b * NPAD * TD + (long long)m * LPER * TD + h * 64 + d;
    float sq = 0.f, sk = 0.f;
    #pragma unroll 4
    for (int r = 0; r < LPER; r++) {
        sq += base[(long long)r * TD];
        sk += base[(long long)r * TD + 512];
    }
    ql[((long long)bh * NLM + m) * DH + d] = sq * (1.f / LPER);
    kl[((long long)bh * NLM + m) * DH + d] = sk * (1.f / LPER);
}

__global__ void softmax_rows(float* __restrict__ data, int cols) {
    __shared__ float sh[8];
    long long row = blockIdx.x;
    float* x = data + row * (long long)cols;
    float m = -1e30f;
    for (int i = threadIdx.x; i < cols; i += 256) m = fmaxf(m, x[i]);
    m = blockReduceMax(m, sh);
    float s = 0.f;
    for (int i = threadIdx.x; i < cols; i += 256) { float e = expf(x[i] - m); x[i] = e; s += e; }
    s = blockReduceSum(s, sh);
    float inv = 1.f / s;
    for (int i = threadIdx.x; i < cols; i += 256) x[i] *= inv;
}

__global__ void reset_kernel() {
    if (threadIdx.x == 0) { g_maxrow = 0; g_maxcol = 0; }
}

__global__ void a2stats_kernel(const float* __restrict__ a2) {
    __shared__ float sh[8];
    int bh = blockIdx.x;
    const float* a = a2 + (long long)bh * NLM * NLM;
    int j = threadIdx.x;
    float cs = 0.f, rs = 0.f;
    for (int i = 0; i < NLM; i++) cs += a[(long long)i * NLM + j];
    const float* row = a + (long long)j * NLM;
    for (int i = 0; i < NLM; i++) rs += row[i];
    float cmax = blockReduceMax(cs, sh);
    float rmax = blockReduceMax(rs, sh);
    if (threadIdx.x == 0) {
        atomicMax(&g_maxcol, __float_as_int(cmax));
        atomicMax(&g_maxrow, __float_as_int(rmax));
    }
}

__global__ void z0_kernel(const float* __restrict__ a2, float* __restrict__ z) {
    __shared__ float tile[32][33];
    int bh = blockIdx.z;
    const float* a = a2 + (long long)bh * NLM * NLM;
    float* zz = z + (long long)bh * NLM * NLM;
    float inv = 1.f / (__int_as_float(g_maxrow) * __int_as_float(g_maxcol));
    int i0 = blockIdx.y * 32, j0 = blockIdx.x * 32;
    for (int r = threadIdx.y; r < 32; r += 8)
        tile[r][threadIdx.x] = a[(long long)(i0 + r) * NLM + j0 + threadIdx.x];
    __syncthreads();
    for (int r = threadIdx.y; r < 32; r += 8)
        zz[(long long)(j0 + r) * NLM + i0 + threadIdx.x] = tile[threadIdx.x][r] * inv;
}

__global__ void reduce16_kernel(const float* __restrict__ part, float* __restrict__ out) {
    long long i = (long long)blockIdx.x * 256 + threadIdx.x;
    const long long stride = (long long)BHN * NLM * DH;
    float s = 0.f;
    #pragma unroll
    for (int k = 0; k < 16; k++) s += part[k * stride + i];
    out[i] = s;
}

__global__ void conv_add_kernel(const float* __restrict__ qkv, const float* __restrict__ w,
                                float* __restrict__ outh) {
    int bh = blockIdx.y;
    int b = bh >> 3, h = bh & 7;
    int iBase = blockIdx.x * 64;
    __shared__ float sv[96][64];
    __shared__ float sw[CONVK];
    const float* vbase = qkv + (long long)b * NPAD * TD + 1024 + h * 64;
    int tid = threadIdx.x;
    for (int idx = tid; idx < 96 * 64; idx += 256) {
        int r = idx >> 6, d = idx & 63;
        int gi = iBase - 16 + r;
        sv[r][d] = (gi >= 0 && gi < NPAD) ? vbase[(long long)gi * TD + d] : 0.f;
    }
    if (tid < CONVK) sw[tid] = w[h * CONVK + tid];
    __syncthreads();
    float* out = outh + (long long)bh * NPAD * DH + (long long)iBase * DH;
    for (int idx = tid; idx < 64 * 64; idx += 256) {
        int r = idx >> 6, d = idx & 63;
        float s = 0.f;
        #pragma unroll
        for (int t = 0; t < CONVK; t++) s += sw[t] * sv[r + t][d];
        out[r * 64 + d] += s;
    }
}

__global__ void merge_kernel(const float* __restrict__ outh, float* __restrict__ cat) {
    long long idx = (long long)blockIdx.x * 256 + threadIdx.x;
    int d = (int)(idx & 63);
    int hh = (int)((idx >> 6) & 7);
    long long rest = idx >> 9;
    int i = (int)(rest & (NPAD - 1));
    int b = (int)(rest >> 13);
    cat[idx] = outh[((long long)(b * NH + hh) * NPAD + i) * DH + d];
}

__global__ void final_kernel(const float* __restrict__ h, const float* __restrict__ gam,
                             const float* __restrict__ bet, const float* __restrict__ w2,
                             const float* __restrict__ b2, float* __restrict__ out) {
    __shared__ float sh[8];
    int b = blockIdx.x;
    const float* x = h + ((long long)b * NPAD + PADN) * DM;
    float s = 0.f, s2 = 0.f;
    for (int i = threadIdx.x; i < DM; i += 256) { float v = x[i]; s += v; s2 += v * v; }
    s = blockReduceSum(s, sh);
    s2 = blockReduceSum(s2, sh);
    float mean = s / DM;
    float var = s2 / DM - mean * mean;
    float inv = rsqrtf(var + 1e-5f);
    float p0 = 0.f, p1 = 0.f;
    for (int i = threadIdx.x; i < DM; i += 256) {
        float hn = (x[i] - mean) * inv * gam[i] + bet[i];
        p0 += hn * w2[2 * i];
        p1 += hn * w2[2 * i + 1];
    }
    p0 = blockReduceSum(p0, sh);
    p1 = blockReduceSum(p1, sh);
    if (threadIdx.x == 0) {
        float l0 = p0 + b2[0], l1 = p1 + b2[1];
        float mx = fmaxf(l0, l1);
        float e0 = expf(l0 - mx), e1 = expf(l1 - mx);
        float si = 1.f / (e0 + e1);
        out[b * 2 + 0] = l0;
        out[b * 2 + 1] = l1;
        out[4 + b * 2 + 0] = e0 * si;
        out[4 + b * 2 + 1] = e1 * si;
        out[8 + b] = (l1 > l0) ? 1.f : 0.f;
    }
}

// ---------------- host side ----------------
static void launch_gemm(int bn, const float* A, const float* B, float* C,
                        int M, int N, int K, int lda, int ldb, int ldc,
                        long long aO, long long aI, int aC,
                        long long bO, long long bI, int bC,
                        long long cS, int batches, float alpha,
                        const float* bias, int relu, int accum, int transB,
                        int splitK = 1, long long partStride = 0,
                        float diagVal = 0.f, float* C2 = nullptr, float diag2 = 0.f) {
    dim3 grid(N / bn, (M + BM - 1) / BM, batches * splitK);
    if (bn == 128)
        gemm_tc<128, 2, 4><<<grid, 256>>>(A, B, C, M, N, K, lda, ldb, ldc,
                                          aO, aI, aC, bO, bI, bC, cS, alpha, bias,
                                          relu, accum, transB, splitK, partStride,
                                          diagVal, C2, diag2);
    else
        gemm_tc<64, 4, 2><<<grid, 256>>>(A, B, C, M, N, K, lda, ldb, ldc,
                                         aO, aI, aC, bO, bI, bC, cS, alpha, bias,
                                         relu, accum, transB, splitK, partStride,
                                         diagVal, C2, diag2);
}

#define SYM(p, s) do { void* _t; cudaGetSymbolAddress(&_t, s); p = (float*)_t; } while (0)

extern "C" void kernel_launch(void* const* d_in, const int* in_sizes, int n_in,
                              void* d_out, int out_size) {
    const float* feats = (const float*)d_in[0];
    const float* fc1_w = (const float*)d_in[1];
    const float* fc1_b = (const float*)d_in[2];
    const float* cls   = (const float*)d_in[3];
    const float* lng[2]   = {(const float*)d_in[4],  (const float*)d_in[10]};
    const float* lnb[2]   = {(const float*)d_in[5],  (const float*)d_in[11]};
    const float* qkvw[2]  = {(const float*)d_in[6],  (const float*)d_in[12]};
    const float* outw[2]  = {(const float*)d_in[7],  (const float*)d_in[13]};
    const float* outb[2]  = {(const float*)d_in[8],  (const float*)d_in[14]};
    const float* convw[2] = {(const float*)d_in[9],  (const float*)d_in[15]};
    const float* nfg  = (const float*)d_in[16];
    const float* nfb  = (const float*)d_in[17];
    const float* fc2w = (const float*)d_in[18];
    const float* fc2b = (const float*)d_in[19];

    float *h, *xln, *qkv, *ql, *kl, *a1, *a3, *a2, *z, *z2, *xz, *t, *t2, *a3v, *w, *a3vp, *outh, *cat;
    SYM(h, g_h); SYM(xln, g_xln); SYM(qkv, g_qkv); SYM(ql, g_ql); SYM(kl, g_kl);
    SYM(a1, g_a1); SYM(a3, g_a3); SYM(a2, g_a2); SYM(z, g_z); SYM(z2, g_z2);
    SYM(xz, g_xz); SYM(t, g_t); SYM(t2, g_t2); SYM(a3v, g_a3v); SYM(w, g_w);
    SYM(a3vp, g_a3vp); SYM(outh, g_outh); SYM(cat, g_cat);

    init_h_kernel<<<dim3(PADN + 1, BATCH), 256>>>(cls, h);

    // fc1 + relu
    launch_gemm(128, feats, fc1_w, h + (long long)(PADN + 1) * DM,
                NTOK, DM, DIN, DIN, DM, DM,
                (long long)NTOK * DIN, 0, 1, 0, 0, 1,
                (long long)NPAD * DM, BATCH, 1.f, fc1_b, 1, 0, 0);

    const long long MM = (long long)NLM * NLM;

    for (int l = 0; l < 2; l++) {
        layernorm_kernel<<<BATCH * NPAD, 256>>>(h, xln, lng[l], lnb[l]);

        // qkv
        launch_gemm(128, xln, qkvw[l], qkv, NPAD, TD, DM, DM, TD, TD,
                    (long long)NPAD * DM, 0, 1, 0, 0, 1,
                    (long long)NPAD * TD, BATCH, 1.f, nullptr, 0, 0, 0);

        landmark_kernel<<<dim3(NLM, BHN), 64>>>(qkv, ql, kl);

        // a1 = softmax(0.125 * Q @ k_l^T)
        launch_gemm(128, qkv, kl, a1, NPAD, NLM, DH, TD, DH, NLM,
                    (long long)NPAD * TD, 64, NH,
                    (long long)NLM * DH, 0, 1,
                    (long long)NPAD * NLM, BHN, 0.125f, nullptr, 0, 0, 1);
        softmax_rows<<<BHN * NPAD, 256>>>(a1, NLM);

        // a2 = softmax(0.125 * q_l @ k_l^T)
        launch_gemm(128, ql, kl, a2, NLM, NLM, DH, DH, DH, NLM,
                    (long long)NLM * DH, 0, 1,
                    (long long)NLM * DH, 0, 1,
                    MM, BHN, 0.125f, nullptr, 0, 0, 1);
        softmax_rows<<<BHN * NLM, 256>>>(a2, NLM);

        // a3 = softmax(0.125 * q_l @ K^T)
        launch_gemm(128, ql, qkv + DM, a3, NLM, NPAD, DH, DH, TD, NPAD,
                    (long long)NLM * DH, 0, 1,
                    (long long)NPAD * TD, 64, NH,
                    (long long)NLM * NPAD, BHN, 0.125f, nullptr, 0, 0, 1);
        softmax_rows<<<BHN * NLM, 256>>>(a3, NPAD);

        // pinv(a2)
        reset_kernel<<<1, 32>>>();
        a2stats_kernel<<<BHN, 256>>>(a2);
        z0_kernel<<<dim3(8, 8, BHN), dim3(32, 8)>>>(a2, z);
        float* zc = z;
        float* zn = z2;
        for (int it = 0; it < 6; it++) {
            // xz = a2@zc ; t = 7I - xz
            launch_gemm(64, a2, zc, xz, NLM, NLM, NLM, NLM, NLM, NLM,
                        MM, 0, 1, MM, 0, 1, MM, BHN, 1.f, nullptr, 0, 0, 0,
                        1, 0, 0.f, t, 7.f);
            // t2 = 15I - xz@t
            launch_gemm(64, xz, t, t2, NLM, NLM, NLM, NLM, NLM, NLM,
                        MM, 0, 1, MM, 0, 1, MM, BHN, -1.f, nullptr, 0, 0, 0,
                        1, 0, 15.f);
            // t = 13I - xz@t2
            launch_gemm(64, xz, t2, t, NLM, NLM, NLM, NLM, NLM, NLM,
                        MM, 0, 1, MM, 0, 1, MM, BHN, -1.f, nullptr, 0, 0, 0,
                        1, 0, 13.f);
            // zn = 0.25 * zc@t
            launch_gemm(64, zc, t, zn, NLM, NLM, NLM, NLM, NLM, NLM,
                        MM, 0, 1, MM, 0, 1, MM, BHN, 0.25f, nullptr, 0, 0, 0);
            float* tmp = zc; zc = zn; zn = tmp;
        }

        // a3v = a3 @ V (split-K 16 + deterministic reduce)
        launch_gemm(64, a3, qkv + 2 * DM, a3vp, NLM, DH, NPAD, NPAD, TD, DH,
                    (long long)NLM * NPAD, 0, 1,
                    (long long)NPAD * TD, 64, NH,
                    (long long)NLM * DH, BHN, 1.f, nullptr, 0, 0, 0,
                    16, (long long)BHN * NLM * DH);
        reduce16_kernel<<<(BHN * NLM * DH) / 256, 256>>>(a3vp, a3v);

        // w = pinv(a2) @ a3v
        launch_gemm(64, zc, a3v, w, NLM, DH, NLM, NLM, DH, DH,
                    MM, 0, 1,
                    (long long)NLM * DH, 0, 1,
                    (long long)NLM * DH, BHN, 1.f, nullptr, 0, 0, 0);

        // outh = a1 @ w
        launch_gemm(64, a1, w, outh, NPAD, DH, NLM, NLM, DH, DH,
                    (long long)NPAD * NLM, 0, 1,
                    (long long)NLM * DH, 0, 1,
                    (long long)NPAD * DH, BHN, 1.f, nullptr, 0, 0, 0);

        // depthwise conv residual on V
        conv_add_kernel<<<dim3(NPAD / 64, BHN), 256>>>(qkv, convw[l], outh);

        merge_kernel<<<(int)(((long long)BATCH * NPAD * DM) / 256), 256>>>(outh, cat);

        // output projection, accumulate into residual stream
        launch_gemm(128, cat + (long long)PADN * DM, outw[l], h + (long long)PADN * DM,
                    NP1, DM, DM, DM, DM, DM,
                    (long long)NPAD * DM, 0, 1, 0, 0, 1,
                    (long long)NPAD * DM, BATCH, 1.f, outb[l], 0, 1, 0);
    }

    final_kernel<<<BATCH, 256>>>(h, nfg, nfb, fc2w, fc2b, (float*)d_out);
}

// round 5
// speedup vs baseline: 2.3586x; 1.0096x over previous
#include <cuda_runtime.h>
#include <cuda_bf16.h>
#include <cstdint>
#include <math.h>

#define BATCH 2
#define NTOK  8000
#define NP1   8001
#define PADN  191
#define NPAD  8192
#define DM    512
#define DIN   1024
#define NH    8
#define DH    64
#define NLM   256
#define LPER  32
#define BHN   16
#define CONVK 33
#define TD    1536
#define BM    128
#define BK    32

// ---------------- scratch ----------------
__device__ float g_h   [(long long)BATCH*NPAD*DM];
__device__ float g_xln [(long long)BATCH*NPAD*DM];
__device__ float g_qkv [(long long)BATCH*NPAD*TD];
__device__ float g_ql  [(long long)BHN*NLM*DH];
__device__ float g_kl  [(long long)BHN*NLM*DH];
__device__ float g_a1  [(long long)BHN*NPAD*NLM];
__device__ float g_a3  [(long long)BHN*NLM*NPAD];
__device__ float g_a2  [(long long)BHN*NLM*NLM];
__device__ float g_z   [(long long)BHN*NLM*NLM];
__device__ float g_z2  [(long long)BHN*NLM*NLM];
__device__ float g_xz  [(long long)BHN*NLM*NLM];
__device__ float g_t   [(long long)BHN*NLM*NLM];
__device__ float g_t2  [(long long)BHN*NLM*NLM];
__device__ float g_a3v [(long long)BHN*NLM*DH];
__device__ float g_w   [(long long)BHN*NLM*DH];
__device__ float g_a3vp[(long long)16*BHN*NLM*DH];
__device__ float g_outh[(long long)BHN*NPAD*DH];
__device__ float g_cat [(long long)BATCH*NPAD*DM];
__device__ int   g_maxrow;
__device__ int   g_maxcol;

// ---------------- reductions ----------------
__device__ __forceinline__ float blockReduceSum(float v, float* sh) {
    #pragma unroll
    for (int o = 16; o; o >>= 1) v += __shfl_xor_sync(0xffffffffu, v, o);
    int w = threadIdx.x >> 5;
    if ((threadIdx.x & 31) == 0) sh[w] = v;
    __syncthreads();
    if (threadIdx.x < 8) {
        v = sh[threadIdx.x];
        #pragma unroll
        for (int o = 4; o; o >>= 1) v += __shfl_xor_sync(0xffu, v, o);
        if (threadIdx.x == 0) sh[0] = v;
    }
    __syncthreads();
    float r = sh[0];
    __syncthreads();
    return r;
}
__device__ __forceinline__ float blockReduceMax(float v, float* sh) {
    #pragma unroll
    for (int o = 16; o; o >>= 1) v = fmaxf(v, __shfl_xor_sync(0xffffffffu, v, o));
    int w = threadIdx.x >> 5;
    if ((threadIdx.x & 31) == 0) sh[w] = v;
    __syncthreads();
    if (threadIdx.x < 8) {
        v = sh[threadIdx.x];
        #pragma unroll
        for (int o = 4; o; o >>= 1) v = fmaxf(v, __shfl_xor_sync(0xffu, v, o));
        if (threadIdx.x == 0) sh[0] = v;
    }
    __syncthreads();
    float r = sh[0];
    __syncthreads();
    return r;
}

// ---------------- tensor-core helpers ----------------
__device__ __forceinline__ void mma16816(float* c, const unsigned* a, const unsigned* b) {
    asm volatile(
        "mma.sync.aligned.m16n8k16.row.col.f32.bf16.bf16.f32 "
        "{%0,%1,%2,%3},{%4,%5,%6,%7},{%8,%9},{%0,%1,%2,%3};\n"
        : "+f"(c[0]), "+f"(c[1]), "+f"(c[2]), "+f"(c[3])
        : "r"(a[0]), "r"(a[1]), "r"(a[2]), "r"(a[3]), "r"(b[0]), "r"(b[1]));
}
__device__ __forceinline__ void ldsm4(unsigned& r0, unsigned& r1, unsigned& r2, unsigned& r3,
                                      uint32_t addr) {
    asm volatile("ldmatrix.sync.aligned.m8n8.x4.shared.b16 {%0,%1,%2,%3}, [%4];\n"
                 : "=r"(r0), "=r"(r1), "=r"(r2), "=r"(r3) : "r"(addr));
}
__device__ __forceinline__ void ldsm4t(unsigned& r0, unsigned& r1, unsigned& r2, unsigned& r3,
                                       uint32_t addr) {
    asm volatile("ldmatrix.sync.aligned.m8n8.x4.trans.shared.b16 {%0,%1,%2,%3}, [%4];\n"
                 : "=r"(r0), "=r"(r1), "=r"(r2), "=r"(r3) : "r"(addr));
}
__device__ __forceinline__ void split2(float x, float y, unsigned& hi, unsigned& lo) {
    __nv_bfloat162 h = __floats2bfloat162_rn(x, y);
    __nv_bfloat162 l = __floats2bfloat162_rn(x - __bfloat162float(h.x),
                                             y - __bfloat162float(h.y));
    hi = *reinterpret_cast<unsigned*>(&h);
    lo = *reinterpret_cast<unsigned*>(&l);
}

// ---------------- tensor-core GEMM (bf16x3, fp32 io, 2-stage pipeline) ----------------
// C = alpha*A@B(^T) + diag*I (+bias)(+relu)(+=C); optional C2 = diag2*I - C.
// Constraints: N % BN == 0, (K/splitK) % 32 == 0. M arbitrary.
template<int BN, int WROWS, int WCOLS>
__global__ void __launch_bounds__(256) gemm_tc(
    const float* __restrict__ A, const float* __restrict__ B, float* __restrict__ C,
    int Mn, int Nn, int Kn, int lda, int ldb, int ldc,
    long long aOuter, long long aInner, int aCnt,
    long long bOuter, long long bInner, int bCnt,
    long long cStride, float alpha, const float* __restrict__ bias,
    int relu, int accum, int transB, int splitK, long long partStride,
    float diagVal, float* __restrict__ C2, float diag2)
{
    constexpr int WM = BM / WROWS;
    constexpr int WN = BN / WCOLS;
    constexpr int MT = WM / 16;
    constexpr int NT = WN / 8;
    constexpr int NTP = WN / 16;
    constexpr int NBJ = BN / 32;
    constexpr int KST = BN + 8;            // k-major B row stride (elements)
    constexpr int ASTG = 2 * BM * 40;      // elements per A stage
    constexpr int BSTG = 2 * BN * 40;      // elements per B stage

    int bz = blockIdx.z;
    int batch = bz / splitK;
    int split = bz - batch * splitK;
    const float* Ab = A + (long long)(batch / aCnt) * aOuter + (long long)(batch % aCnt) * aInner;
    const float* Bb = B + (long long)(batch / bCnt) * bOuter + (long long)(batch % bCnt) * bInner;
    float* Cb = C + (long long)batch * cStride + (long long)split * partStride;
    float* C2b = C2 ? C2 + (long long)batch * cStride : nullptr;
    int kPer = Kn / splitK;
    int kStart = split * kPer;

    __shared__ __align__(16) __nv_bfloat16 sA[2 * ASTG];
    __shared__ __align__(16) __nv_bfloat16 sB[2 * BSTG];

    uint32_t saBase = (uint32_t)__cvta_generic_to_shared(&sA[0]);
    uint32_t sbBase = (uint32_t)__cvta_generic_to_shared(&sB[0]);

    int tid = threadIdx.x;
    int lane = tid & 31;
    int wid = tid >> 5;
    int lt = lane & 7;
    int lg = lane >> 3;
    int warpM = (wid / WCOLS) * WM;
    int warpN = (wid % WCOLS) * WN;
    int rowBase = blockIdx.y * BM;
    int colBase = blockIdx.x * BN;

    float acc[MT][NT][4];
    #pragma unroll
    for (int i = 0; i < MT; i++)
        #pragma unroll
        for (int j = 0; j < NT; j++)
            #pragma unroll
            for (int e = 0; e < 4; e++) acc[i][j][e] = 0.f;

    int aRow = tid >> 3, aSeg = tid & 7;
    float4 va[4], vb[NBJ];

    auto ldgA = [&](int k0) {
        #pragma unroll
        for (int j = 0; j < 4; j++) {
            int gr = rowBase + aRow + j * 32;
            va[j] = make_float4(0.f, 0.f, 0.f, 0.f);
            if (gr < Mn)
                va[j] = *(const float4*)(Ab + (long long)gr * lda + kStart + k0 + aSeg * 4);
        }
    };
    auto ldgB = [&](int k0) {
        if (transB) {
            #pragma unroll
            for (int j = 0; j < NBJ; j++)
                vb[j] = *(const float4*)(Bb + (long long)(colBase + aRow + j * 32) * ldb +
                                         kStart + k0 + aSeg * 4);
        } else {
            #pragma unroll
            for (int j = 0; j < NBJ; j++) {
                int k, n0;
                if (BN == 128) { k = (tid >> 5) + j * 8;  n0 = (tid & 31) * 4; }
                else           { k = (tid >> 4) + j * 16; n0 = (tid & 15) * 4; }
                vb[j] = *(const float4*)(Bb + (long long)(kStart + k0 + k) * ldb + colBase + n0);
            }
        }
    };
    auto stsA = [&](int stg) {
        __nv_bfloat16* base = &sA[stg * ASTG];
        #pragma unroll
        for (int j = 0; j < 4; j++) {
            int row = aRow + j * 32;
            unsigned h0, h1, l0, l1;
            split2(va[j].x, va[j].y, h0, l0);
            split2(va[j].z, va[j].w, h1, l1);
            *(uint2*)&base[(0 * BM + row) * 40 + aSeg * 4] = make_uint2(h0, h1);
            *(uint2*)&base[(1 * BM + row) * 40 + aSeg * 4] = make_uint2(l0, l1);
        }
    };
    auto stsB = [&](int stg) {
        __nv_bfloat16* base = &sB[stg * BSTG];
        if (transB) {
            #pragma unroll
            for (int j = 0; j < NBJ; j++) {
                int row = aRow + j * 32;
                unsigned h0, h1, l0, l1;
                split2(vb[j].x, vb[j].y, h0, l0);
                split2(vb[j].z, vb[j].w, h1, l1);
                *(uint2*)&base[(0 * BN + row) * 40 + aSeg * 4] = make_uint2(h0, h1);
                *(uint2*)&base[(1 * BN + row) * 40 + aSeg * 4] = make_uint2(l0, l1);
            }
        } else {
            #pragma unroll
            for (int j = 0; j < NBJ; j++) {
                int k, n0;
                if (BN == 128) { k = (tid >> 5) + j * 8;  n0 = (tid & 31) * 4; }
                else           { k = (tid >> 4) + j * 16; n0 = (tid & 15) * 4; }
                unsigned h0, h1, l0, l1;
                split2(vb[j].x, vb[j].y, h0, l0);
                split2(vb[j].z, vb[j].w, h1, l1);
                *(uint2*)&base[(0 * 32 + k) * KST + n0] = make_uint2(h0, h1);
                *(uint2*)&base[(1 * 32 + k) * KST + n0] = make_uint2(l0, l1);
            }
        }
    };

    int nIter = kPer / BK;
    ldgA(0);
    ldgB(0);
    stsA(0);
    stsB(0);
    __syncthreads();

    for (int it = 0; it < nIter; it++) {
        int cur = it & 1;
        bool more = (it + 1 < nIter);
        if (more) { ldgA((it + 1) * BK); ldgB((it + 1) * BK); }

        uint32_t saS = saBase + (cur * ASTG << 1);
        uint32_t sbS = sbBase + (cur * BSTG << 1);

        #pragma unroll
        for (int ks = 0; ks < 2; ks++) {
            int k8 = ks * 16;
            unsigned bh[NTP][4], bl[NTP][4];
            #pragma unroll
            for (int ntp = 0; ntp < NTP; ntp++) {
                if (transB) {
                    int n = warpN + ntp * 16 + lt + ((lg >> 1) << 3);
                    int kk = k8 + ((lg & 1) << 3);
                    ldsm4(bh[ntp][0], bh[ntp][1], bh[ntp][2], bh[ntp][3],
                          sbS + (((0 * BN + n) * 40 + kk) << 1));
                    ldsm4(bl[ntp][0], bl[ntp][1], bl[ntp][2], bl[ntp][3],
                          sbS + (((1 * BN + n) * 40 + kk) << 1));
                } else {
                    int k = k8 + lt + ((lg & 1) << 3);
                    int n = warpN + ntp * 16 + ((lg >> 1) << 3);
                    ldsm4t(bh[ntp][0], bh[ntp][1], bh[ntp][2], bh[ntp][3],
                           sbS + (((0 * 32 + k) * KST + n) << 1));
                    ldsm4t(bl[ntp][0], bl[ntp][1], bl[ntp][2], bl[ntp][3],
                           sbS + (((1 * 32 + k) * KST + n) << 1));
                }
            }
            #pragma unroll
            for (int mt = 0; mt < MT; mt++) {
                unsigned ah[4], al[4];
                int m = warpM + mt * 16 + lt + ((lg & 1) << 3);
                int kk = k8 + ((lg >> 1) << 3);
                ldsm4(ah[0], ah[1], ah[2], ah[3],
                      saS + (((0 * BM + m) * 40 + kk) << 1));
                ldsm4(al[0], al[1], al[2], al[3],
                      saS + (((1 * BM + m) * 40 + kk) << 1));
                #pragma unroll
                for (int nt = 0; nt < NT; nt++) {
                    const unsigned* ph = &bh[nt >> 1][(nt & 1) * 2];
                    const unsigned* pl = &bl[nt >> 1][(nt & 1) * 2];
                    mma16816(acc[mt][nt], ah, ph);
                    mma16816(acc[mt][nt], ah, pl);
                    mma16816(acc[mt][nt], al, ph);
                }
            }
        }
        if (more) { stsA(cur ^ 1); stsB(cur ^ 1); }
        __syncthreads();
    }

    int q = lane & 3, g = lane >> 2;
    #pragma unroll
    for (int mt = 0; mt < MT; mt++) {
        #pragma unroll
        for (int nt = 0; nt < NT; nt++) {
            int r0 = rowBase + warpM + mt * 16 + g;
            int c0 = colBase + warpN + nt * 8 + q * 2;
            #pragma unroll
            for (int e = 0; e < 4; e++) {
                int gr = r0 + ((e >> 1) << 3);
                int gc = c0 + (e & 1);
                if (gr >= Mn) continue;
                float v = alpha * acc[mt][nt][e];
                if (gr == gc) v += diagVal;
                if (bias) v += bias[gc];
                if (relu) v = fmaxf(v, 0.f);
                long long off = (long long)gr * ldc + gc;
                if (accum) v += Cb[off];
                Cb[off] = v;
                if (C2b) C2b[off] = ((gr == gc) ? diag2 : 0.f) - v;
            }
        }
    }
}

// ---------------- misc kernels ----------------
__global__ void init_h_kernel(const float* __restrict__ cls, float* __restrict__ h) {
    int r = blockIdx.x, b = blockIdx.y;
    float* o = h + ((long long)b * NPAD + r) * DM;
    for (int i = threadIdx.x; i < DM; i += 256) o[i] = (r == PADN) ? cls[i] : 0.f;
}

__global__ void layernorm_kernel(const float* __restrict__ in, float* __restrict__ out,
                                 const float* __restrict__ gam, const float* __restrict__ bet) {
    __shared__ float sh[8];
    long long row = blockIdx.x;
    int r = (int)(row % NPAD);
    float* o = out + row * DM;
    if (r < PADN) {
        for (int i = threadIdx.x; i < DM; i += 256) o[i] = 0.f;
        return;
    }
    const float* x = in + row * DM;
    float s = 0.f, s2 = 0.f;
    for (int i = threadIdx.x; i < DM; i += 256) { float v = x[i]; s += v; s2 += v * v; }
    s = blockReduceSum(s, sh);
    s2 = blockReduceSum(s2, sh);
    float mean = s / DM;
    float var = s2 / DM - mean * mean;
    float inv = rsqrtf(var + 1e-5f);
    for (int i = threadIdx.x; i < DM; i += 256) o[i] = (x[i] - mean) * inv * gam[i] + bet[i];
}

__global__ void landmark_kernel(const float* __restrict__ qkv,
                                float* __restrict__ ql, float* __restrict__ kl) {
    int m = blockIdx.x, bh = blockIdx.y;
    int b = bh >> 3, h = bh & 7;
    int d = threadIdx.x;
    const float* base = qkv + (long long)b * NPAD * TD + (long long)m * LPER * TD + h * 64 + d;
    float sq = 0.f, sk = 0.f;
    #pragma unroll 4
    for (int r = 0; r < LPER; r++) {
        sq += base[(long long)r * TD];
        sk += base[(long long)r * TD + 512];
    }
    ql[((long long)bh * NLM + m) * DH + d] = sq * (1.f / LPER);
    kl[((long long)bh * NLM + m) * DH + d] = sk * (1.f / LPER);
}

__global__ void softmax_rows(float* __restrict__ data, int cols) {
    __shared__ float sh[8];
    long long row = blockIdx.x;
    float* x = data + row * (long long)cols;
    float m = -1e30f;
    for (int i = threadIdx.x; i < cols; i += 256) m = fmaxf(m, x[i]);
    m = blockReduceMax(m, sh);
    float s = 0.f;
    for (int i = threadIdx.x; i < cols; i += 256) { float e = expf(x[i] - m); x[i] = e; s += e; }
    s = blockReduceSum(s, sh);
    float inv = 1.f / s;
    for (int i = threadIdx.x; i < cols; i += 256) x[i] *= inv;
}

__global__ void reset_kernel() {
    if (threadIdx.x == 0) { g_maxrow = 0; g_maxcol = 0; }
}

__global__ void a2stats_kernel(const float* __restrict__ a2) {
    __shared__ float sh[8];
    int bh = blockIdx.x;
    const float* a = a2 + (long long)bh * NLM * NLM;
    int j = threadIdx.x;
    float cs = 0.f, rs = 0.f;
    for (int i = 0; i < NLM; i++) cs += a[(long long)i * NLM + j];
    const float* row = a + (long long)j * NLM;
    for (int i = 0; i < NLM; i++) rs += row[i];
    float cmax = blockReduceMax(cs, sh);
    float rmax = blockReduceMax(rs, sh);
    if (threadIdx.x == 0) {
        atomicMax(&g_maxcol, __float_as_int(cmax));
        atomicMax(&g_maxrow, __float_as_int(rmax));
    }
}

__global__ void z0_kernel(const float* __restrict__ a2, float* __restrict__ z) {
    __shared__ float tile[32][33];
    int bh = blockIdx.z;
    const float* a = a2 + (long long)bh * NLM * NLM;
    float* zz = z + (long long)bh * NLM * NLM;
    float inv = 1.f / (__int_as_float(g_maxrow) * __int_as_float(g_maxcol));
    int i0 = blockIdx.y * 32, j0 = blockIdx.x * 32;
    for (int r = threadIdx.y; r < 32; r += 8)
        tile[r][threadIdx.x] = a[(long long)(i0 + r) * NLM + j0 + threadIdx.x];
    __syncthreads();
    for (int r = threadIdx.y; r < 32; r += 8)
        zz[(long long)(j0 + r) * NLM + i0 + threadIdx.x] = tile[threadIdx.x][r] * inv;
}

__global__ void reduce16_kernel(const float* __restrict__ part, float* __restrict__ out) {
    long long i = (long long)blockIdx.x * 256 + threadIdx.x;
    const long long stride = (long long)BHN * NLM * DH;
    float s = 0.f;
    #pragma unroll
    for (int k = 0; k < 16; k++) s += part[k * stride + i];
    out[i] = s;
}

__global__ void conv_add_kernel(const float* __restrict__ qkv, const float* __restrict__ w,
                                float* __restrict__ outh) {
    int bh = blockIdx.y;
    int b = bh >> 3, h = bh & 7;
    int iBase = blockIdx.x * 64;
    __shared__ float sv[96][64];
    __shared__ float sw[CONVK];
    const float* vbase = qkv + (long long)b * NPAD * TD + 1024 + h * 64;
    int tid = threadIdx.x;
    for (int idx = tid; idx < 96 * 64; idx += 256) {
        int r = idx >> 6, d = idx & 63;
        int gi = iBase - 16 + r;
        sv[r][d] = (gi >= 0 && gi < NPAD) ? vbase[(long long)gi * TD + d] : 0.f;
    }
    if (tid < CONVK) sw[tid] = w[h * CONVK + tid];
    __syncthreads();
    float* out = outh + (long long)bh * NPAD * DH + (long long)iBase * DH;
    for (int idx = tid; idx < 64 * 64; idx += 256) {
        int r = idx >> 6, d = idx & 63;
        float s = 0.f;
        #pragma unroll
        for (int t = 0; t < CONVK; t++) s += sw[t] * sv[r + t][d];
        out[r * 64 + d] += s;
    }
}

__global__ void merge_kernel(const float* __restrict__ outh, float* __restrict__ cat) {
    long long idx = (long long)blockIdx.x * 256 + threadIdx.x;
    int d = (int)(idx & 63);
    int hh = (int)((idx >> 6) & 7);
    long long rest = idx >> 9;
    int i = (int)(rest & (NPAD - 1));
    int b = (int)(rest >> 13);
    cat[idx] = outh[((long long)(b * NH + hh) * NPAD + i) * DH + d];
}

__global__ void final_kernel(const float* __restrict__ h, const float* __restrict__ gam,
                             const float* __restrict__ bet, const float* __restrict__ w2,
                             const float* __restrict__ b2, float* __restrict__ out) {
    __shared__ float sh[8];
    int b = blockIdx.x;
    const float* x = h + ((long long)b * NPAD + PADN) * DM;
    float s = 0.f, s2 = 0.f;
    for (int i = threadIdx.x; i < DM; i += 256) { float v = x[i]; s += v; s2 += v * v; }
    s = blockReduceSum(s, sh);
    s2 = blockReduceSum(s2, sh);
    float mean = s / DM;
    float var = s2 / DM - mean * mean;
    float inv = rsqrtf(var + 1e-5f);
    float p0 = 0.f, p1 = 0.f;
    for (int i = threadIdx.x; i < DM; i += 256) {
        float hn = (x[i] - mean) * inv * gam[i] + bet[i];
        p0 += hn * w2[2 * i];
        p1 += hn * w2[2 * i + 1];
    }
    p0 = blockReduceSum(p0, sh);
    p1 = blockReduceSum(p1, sh);
    if (threadIdx.x == 0) {
        float l0 = p0 + b2[0], l1 = p1 + b2[1];
        float mx = fmaxf(l0, l1);
        float e0 = expf(l0 - mx), e1 = expf(l1 - mx);
        float si = 1.f / (e0 + e1);
        out[b * 2 + 0] = l0;
        out[b * 2 + 1] = l1;
        out[4 + b * 2 + 0] = e0 * si;
        out[4 + b * 2 + 1] = e1 * si;
        out[8 + b] = (l1 > l0) ? 1.f : 0.f;
    }
}

// ---------------- host side ----------------
static void launch_gemm(int bn, const float* A, const float* B, float* C,
                        int M, int N, int K, int lda, int ldb, int ldc,
                        long long aO, long long aI, int aC,
                        long long bO, long long bI, int bC,
                        long long cS, int batches, float alpha,
                        const float* bias, int relu, int accum, int transB,
                        int splitK = 1, long long partStride = 0,
                        float diagVal = 0.f, float* C2 = nullptr, float diag2 = 0.f) {
    dim3 grid(N / bn, (M + BM - 1) / BM, batches * splitK);
    if (bn == 128)
        gemm_tc<128, 2, 4><<<grid, 256>>>(A, B, C, M, N, K, lda, ldb, ldc,
                                          aO, aI, aC, bO, bI, bC, cS, alpha, bias,
                                          relu, accum, transB, splitK, partStride,
                                          diagVal, C2, diag2);
    else
        gemm_tc<64, 4, 2><<<grid, 256>>>(A, B, C, M, N, K, lda, ldb, ldc,
                                         aO, aI, aC, bO, bI, bC, cS, alpha, bias,
                                         relu, accum, transB, splitK, partStride,
                                         diagVal, C2, diag2);
}

#define SYM(p, s) do { void* _t; cudaGetSymbolAddress(&_t, s); p = (float*)_t; } while (0)

extern "C" void kernel_launch(void* const* d_in, const int* in_sizes, int n_in,
                              void* d_out, int out_size) {
    const float* feats = (const float*)d_in[0];
    const float* fc1_w = (const float*)d_in[1];
    const float* fc1_b = (const float*)d_in[2];
    const float* cls   = (const float*)d_in[3];
    const float* lng[2]   = {(const float*)d_in[4],  (const float*)d_in[10]};
    const float* lnb[2]   = {(const float*)d_in[5],  (const float*)d_in[11]};
    const float* qkvw[2]  = {(const float*)d_in[6],  (const float*)d_in[12]};
    const float* outw[2]  = {(const float*)d_in[7],  (const float*)d_in[13]};
    const float* outb[2]  = {(const float*)d_in[8],  (const float*)d_in[14]};
    const float* convw[2] = {(const float*)d_in[9],  (const float*)d_in[15]};
    const float* nfg  = (const float*)d_in[16];
    const float* nfb  = (const float*)d_in[17];
    const float* fc2w = (const float*)d_in[18];
    const float* fc2b = (const float*)d_in[19];

    float *h, *xln, *qkv, *ql, *kl, *a1, *a3, *a2, *z, *z2, *xz, *t, *t2, *a3v, *w, *a3vp, *outh, *cat;
    SYM(h, g_h); SYM(xln, g_xln); SYM(qkv, g_qkv); SYM(ql, g_ql); SYM(kl, g_kl);
    SYM(a1, g_a1); SYM(a3, g_a3); SYM(a2, g_a2); SYM(z, g_z); SYM(z2, g_z2);
    SYM(xz, g_xz); SYM(t, g_t); SYM(t2, g_t2); SYM(a3v, g_a3v); SYM(w, g_w);
    SYM(a3vp, g_a3vp); SYM(outh, g_outh); SYM(cat, g_cat);

    init_h_kernel<<<dim3(PADN + 1, BATCH), 256>>>(cls, h);

    // fc1 + relu
    launch_gemm(128, feats, fc1_w, h + (long long)(PADN + 1) * DM,
                NTOK, DM, DIN, DIN, DM, DM,
                (long long)NTOK * DIN, 0, 1, 0, 0, 1,
                (long long)NPAD * DM, BATCH, 1.f, fc1_b, 1, 0, 0);

    const long long MM = (long long)NLM * NLM;

    for (int l = 0; l < 2; l++) {
        layernorm_kernel<<<BATCH * NPAD, 256>>>(h, xln, lng[l], lnb[l]);

        // qkv
        launch_gemm(128, xln, qkvw[l], qkv, NPAD, TD, DM, DM, TD, TD,
                    (long long)NPAD * DM, 0, 1, 0, 0, 1,
                    (long long)NPAD * TD, BATCH, 1.f, nullptr, 0, 0, 0);

        landmark_kernel<<<dim3(NLM, BHN), 64>>>(qkv, ql, kl);

        // a1 = softmax(0.125 * Q @ k_l^T)
        launch_gemm(128, qkv, kl, a1, NPAD, NLM, DH, TD, DH, NLM,
                    (long long)NPAD * TD, 64, NH,
                    (long long)NLM * DH, 0, 1,
                    (long long)NPAD * NLM, BHN, 0.125f, nullptr, 0, 0, 1);
        softmax_rows<<<BHN * NPAD, 256>>>(a1, NLM);

        // a2 = softmax(0.125 * q_l @ k_l^T)
        launch_gemm(128, ql, kl, a2, NLM, NLM, DH, DH, DH, NLM,
                    (long long)NLM * DH, 0, 1,
                    (long long)NLM * DH, 0, 1,
                    MM, BHN, 0.125f, nullptr, 0, 0, 1);
        softmax_rows<<<BHN * NLM, 256>>>(a2, NLM);

        // a3 = softmax(0.125 * q_l @ K^T)
        launch_gemm(128, ql, qkv + DM, a3, NLM, NPAD, DH, DH, TD, NPAD,
                    (long long)NLM * DH, 0, 1,
                    (long long)NPAD * TD, 64, NH,
                    (long long)NLM * NPAD, BHN, 0.125f, nullptr, 0, 0, 1);
        softmax_rows<<<BHN * NLM, 256>>>(a3, NPAD);

        // pinv(a2)
        reset_kernel<<<1, 32>>>();
        a2stats_kernel<<<BHN, 256>>>(a2);
        z0_kernel<<<dim3(8, 8, BHN), dim3(32, 8)>>>(a2, z);
        float* zc = z;
        float* zn = z2;
        for (int it = 0; it < 6; it++) {
            // xz = a2@zc ; t = 7I - xz
            launch_gemm(64, a2, zc, xz, NLM, NLM, NLM, NLM, NLM, NLM,
                        MM, 0, 1, MM, 0, 1, MM, BHN, 1.f, nullptr, 0, 0, 0,
                        1, 0, 0.f, t, 7.f);
            // t2 = 15I - xz@t
            launch_gemm(64, xz, t, t2, NLM, NLM, NLM, NLM, NLM, NLM,
                        MM, 0, 1, MM, 0, 1, MM, BHN, -1.f, nullptr, 0, 0, 0,
                        1, 0, 15.f);
            // t = 13I - xz@t2
            launch_gemm(64, xz, t2, t, NLM, NLM, NLM, NLM, NLM, NLM,
                        MM, 0, 1, MM, 0, 1, MM, BHN, -1.f, nullptr, 0, 0, 0,
                        1, 0, 13.f);
            // zn = 0.25 * zc@t
            launch_gemm(64, zc, t, zn, NLM, NLM, NLM, NLM, NLM, NLM,
                        MM, 0, 1, MM, 0, 1, MM, BHN, 0.25f, nullptr, 0, 0, 0);
            float* tmp = zc; zc = zn; zn = tmp;
        }

        // a3v = a3 @ V (split-K 16 + deterministic reduce)
        launch_gemm(64, a3, qkv + 2 * DM, a3vp, NLM, DH, NPAD, NPAD, TD, DH,
                    (long long)NLM * NPAD, 0, 1,
                    (long long)NPAD * TD, 64, NH,
                    (long long)NLM * DH, BHN, 1.f, nullptr, 0, 0, 0,
                    16, (long long)BHN * NLM * DH);
        reduce16_kernel<<<(BHN * NLM * DH) / 256, 256>>>(a3vp, a3v);

        // w = pinv(a2) @ a3v
        launch_gemm(64, zc, a3v, w, NLM, DH, NLM, NLM, DH, DH,
                    MM, 0, 1,
                    (long long)NLM * DH, 0, 1,
                    (long long)NLM * DH, BHN, 1.f, nullptr, 0, 0, 0);

        // outh = a1 @ w
        launch_gemm(64, a1, w, outh, NPAD, DH, NLM, NLM, DH, DH,
                    (long long)NPAD * NLM, 0, 1,
                    (long long)NLM * DH, 0, 1,
                    (long long)NPAD * DH, BHN, 1.f, nullptr, 0, 0, 0);

        // depthwise conv residual on V
        conv_add_kernel<<<dim3(NPAD / 64, BHN), 256>>>(qkv, convw[l], outh);

        merge_kernel<<<(int)(((long long)BATCH * NPAD * DM) / 256), 256>>>(outh, cat);

        // output projection, accumulate into residual stream
        launch_gemm(128, cat + (long long)PADN * DM, outw[l], h + (long long)PADN * DM,
                    NP1, DM, DM, DM, DM, DM,
                    (long long)NPAD * DM, 0, 1, 0, 0, 1,
                    (long long)NPAD * DM, BATCH, 1.f, outb[l], 0, 1, 0);
    }

    final_kernel<<<BATCH, 256>>>(h, nfg, nfb, fc2w, fc2b, (float*)d_out);
}